// round 13
// baseline (speedup 1.0000x reference)
#include <cuda_runtime.h>
#include <cuda_bf16.h>
#include <cuda_fp16.h>
#include <cstdint>

#define TOKENS 131072            // 8 * 128 * 128
#define DIM 256

// scale * log2(e) folded into Q at GEMM0 epilogue
#define K2SCALE 0.25503837897544077f

// ---------------------------------------------------------------------------
// Scratch (device globals — no cudaMalloc allowed)
// ---------------------------------------------------------------------------
__device__ __nv_bfloat16 g_qkv[(size_t)TOKENS * 3 * DIM];     // 192 MiB (bf16)
__device__ __half g_h[(size_t)TOKENS * DIM];                  //  64 MiB (f16 now)
__device__ __nv_bfloat16 g_WqkvT[3 * DIM * DIM];              // [768][256] bf16
__device__ __half g_WprojT[DIM * DIM];                        // [256][256] f16

// ---------------------------------------------------------------------------
// PTX helpers
// ---------------------------------------------------------------------------
__device__ __forceinline__ void mma_bf16(float* c, const uint32_t* a, const uint32_t* b) {
    asm("mma.sync.aligned.m16n8k16.row.col.f32.bf16.bf16.f32 "
        "{%0,%1,%2,%3}, {%4,%5,%6,%7}, {%8,%9}, {%0,%1,%2,%3};\n"
        : "+f"(c[0]), "+f"(c[1]), "+f"(c[2]), "+f"(c[3])
        : "r"(a[0]), "r"(a[1]), "r"(a[2]), "r"(a[3]), "r"(b[0]), "r"(b[1]));
}

// f16 x f16 -> f16 accumulate (probe: possibly double-rate vs f32 accum)
__device__ __forceinline__ void mma_f16acc(uint32_t* c, const uint32_t* a, const uint32_t* b) {
    asm("mma.sync.aligned.m16n8k16.row.col.f16.f16.f16.f16 "
        "{%0,%1}, {%2,%3,%4,%5}, {%6,%7}, {%0,%1};\n"
        : "+r"(c[0]), "+r"(c[1])
        : "r"(a[0]), "r"(a[1]), "r"(a[2]), "r"(a[3]), "r"(b[0]), "r"(b[1]));
}

__device__ __forceinline__ void ldsm_x4(uint32_t* r, uint32_t addr) {
    asm volatile("ldmatrix.sync.aligned.m8n8.x4.shared.b16 {%0,%1,%2,%3}, [%4];"
                 : "=r"(r[0]), "=r"(r[1]), "=r"(r[2]), "=r"(r[3]) : "r"(addr));
}

__device__ __forceinline__ void cp_async16(void* smem_ptr, const void* gmem_ptr) {
    uint32_t s = (uint32_t)__cvta_generic_to_shared(smem_ptr);
    asm volatile("cp.async.cg.shared.global [%0], [%1], 16;\n" :: "r"(s), "l"(gmem_ptr));
}

__device__ __forceinline__ uint32_t pack_bf(float x, float y) {
    __nv_bfloat162 h = __floats2bfloat162_rn(x, y);
    return *reinterpret_cast<uint32_t*>(&h);
}

__device__ __forceinline__ float ex2_fast(float x) {
    float y;
    asm("ex2.approx.f32 %0, %1;" : "=f"(y) : "f"(x));
    return y;
}

// swizzled chunk offsets. A rows = 512B (32 chunks); B rows = 128B (8 chunks).
__device__ __forceinline__ uint32_t a_sw(int row, int c16) {   // bytes
    return (uint32_t)(row * 512 + ((c16 ^ (row & 7)) << 4));
}
__device__ __forceinline__ uint32_t b_sw(int row, int c16) {   // bytes
    return (uint32_t)(row * 128 + ((c16 ^ (row & 7)) << 4));
}

// ---------------------------------------------------------------------------
// Weight prep: Wqkv -> bf16 transpose; Wproj -> f16 transpose (tiny)
// ---------------------------------------------------------------------------
__global__ void prep_weights(const float* __restrict__ Wqkv, const float* __restrict__ Wproj) {
    int n = blockIdx.x;        // 0..767
    int k = threadIdx.x;       // 0..255
    g_WqkvT[n * DIM + k] = __float2bfloat16(Wqkv[(size_t)k * 768 + n]);
    if (n < DIM)
        g_WprojT[n * DIM + k] = __float2half(Wproj[(size_t)k * DIM + n]);
}

// ---------------------------------------------------------------------------
// GEMM0 (bf16, persistent over N, LN fused, 3-stage B pipeline) — R10 state.
// qkv[M,768] = LN(x)[M,256] x Wqkv (+bqkv).
// smem total: 65536 + 49152 = 114688 B  (2 CTAs/SM)
// ---------------------------------------------------------------------------
#define GEMM0_SMEM 114688

__global__ __launch_bounds__(256, 2) void gemm0_persist(const float* __restrict__ x,
                                                        const float* __restrict__ gamma,
                                                        const float* __restrict__ beta,
                                                        const float* __restrict__ bias) {
    extern __shared__ char smraw[];
    __nv_bfloat16* smA = (__nv_bfloat16*)smraw;            // A: [0, 65536) bytes
    char* smB = smraw + 65536;                             // B stage s at s*16384

    int m0 = blockIdx.x * 128;
    int tid = threadIdx.x;
    int lane = tid & 31, warp = tid >> 5;
    int wm = warp >> 2, wn = warp & 3;   // 2 x 4 warp grid
    int g = lane >> 2, t = lane & 3;

    int arow = lane & 15;
    int acol = (lane >> 4) << 3;
    int brow = (lane & 7) + ((lane >> 4) << 3);
    int bcol = (lane & 8) ? 8 : 0;
    uint32_t aBase = (uint32_t)__cvta_generic_to_shared(smraw);
    uint32_t bBase0 = aBase + 65536;

    auto load_B = [&](int f, int st) {     // f -> (it, kb)
        int it = f >> 2, kb = f & 3;
#pragma unroll
        for (int i = 0; i < 4; i++) {
            int li = tid + i * 256;           // 0..1023
            int row = li >> 3, c16 = li & 7;  // 128 rows x 8 chunks
            cp_async16(smB + st * 16384 + b_sw(row, c16),
                       &g_WqkvT[(size_t)(it * 128 + row) * 256 + kb * 64 + c16 * 8]);
        }
        asm volatile("cp.async.commit_group;\n" ::: "memory");
    };

    load_B(0, 0);
    load_B(1, 1);

    // ---- LN prologue: 8 warps x 16 rows, write swizzled bf16 A tile ----
    {
        int c0 = lane * 8;                   // chunk index = lane
        float4 ga = *(const float4*)(gamma + c0);
        float4 gb = *(const float4*)(gamma + c0 + 4);
        float4 ba = *(const float4*)(beta + c0);
        float4 bb = *(const float4*)(beta + c0 + 4);
        float gg[8] = {ga.x, ga.y, ga.z, ga.w, gb.x, gb.y, gb.z, gb.w};
        float be[8] = {ba.x, ba.y, ba.z, ba.w, bb.x, bb.y, bb.z, bb.w};
#pragma unroll 4
        for (int i = 0; i < 16; i++) {
            int row = warp * 16 + i;
            const float* xr = x + (size_t)(m0 + row) * 256 + c0;
            float4 v0 = *(const float4*)xr;
            float4 v1 = *(const float4*)(xr + 4);
            float v[8] = {v0.x, v0.y, v0.z, v0.w, v1.x, v1.y, v1.z, v1.w};
            float s = 0.f, sq = 0.f;
#pragma unroll
            for (int j = 0; j < 8; j++) { s += v[j]; sq += v[j] * v[j]; }
#pragma unroll
            for (int o = 16; o > 0; o >>= 1) {
                s  += __shfl_xor_sync(0xffffffffu, s, o);
                sq += __shfl_xor_sync(0xffffffffu, sq, o);
            }
            float mean = s * (1.0f / DIM);
            float var  = sq * (1.0f / DIM) - mean * mean;
            float rstd = rsqrtf(var + 1e-5f);
            __nv_bfloat16 y[8];
#pragma unroll
            for (int j = 0; j < 8; j++)
                y[j] = __float2bfloat16((v[j] - mean) * rstd * gg[j] + be[j]);
            *(uint4*)((char*)smA + a_sw(row, lane)) = *(uint4*)y;
        }
    }

    float acc[4][4][4];
#pragma unroll
    for (int i = 0; i < 4; i++)
#pragma unroll
        for (int j = 0; j < 4; j++)
#pragma unroll
            for (int k = 0; k < 4; k++) acc[i][j][k] = 0.f;

    for (int f = 0; f < 24; f++) {
        int it = f >> 2, kb = f & 3;
        int st = f % 3;
        asm volatile("cp.async.wait_group 1;\n" ::: "memory");
        __syncthreads();
        if (f + 2 < 24) load_B(f + 2, (f + 2) % 3);

        uint32_t bB = bBase0 + st * 16384;

#pragma unroll
        for (int ks = 0; ks < 4; ks++) {
            int c16a = (kb * 64 + ks * 16 + acol) >> 3;
            int c16b = (ks * 16 + bcol) >> 3;
            uint32_t af[4][4], bfr[4][2];
#pragma unroll
            for (int mt = 0; mt < 4; mt++) {
                int r = wm * 64 + mt * 16 + arow;
                ldsm_x4(af[mt], aBase + a_sw(r, c16a));
            }
#pragma unroll
            for (int p = 0; p < 2; p++) {
                int r = wn * 32 + p * 16 + brow;
                uint32_t r4[4];
                ldsm_x4(r4, bB + b_sw(r, c16b));
                bfr[2 * p][0] = r4[0]; bfr[2 * p][1] = r4[1];
                bfr[2 * p + 1][0] = r4[2]; bfr[2 * p + 1][1] = r4[3];
            }
#pragma unroll
            for (int mt = 0; mt < 4; mt++)
#pragma unroll
                for (int nt = 0; nt < 4; nt++)
                    mma_bf16(acc[mt][nt], af[mt], bfr[nt]);
        }

        if (kb == 3) {
            int n0 = it * 128;
            float sc = (it < 2) ? K2SCALE : 1.0f;   // Q scaled; K, V plain
#pragma unroll
            for (int mt = 0; mt < 4; mt++) {
                int r = m0 + wm * 64 + mt * 16 + g;
#pragma unroll
                for (int nt = 0; nt < 4; nt++) {
                    int c = n0 + wn * 32 + nt * 8 + t * 2;
                    float b0 = bias[c], b1 = bias[c + 1];
                    *reinterpret_cast<__nv_bfloat162*>(&g_qkv[(size_t)r * 768 + c]) =
                        __floats2bfloat162_rn((acc[mt][nt][0] + b0) * sc,
                                              (acc[mt][nt][1] + b1) * sc);
                    *reinterpret_cast<__nv_bfloat162*>(&g_qkv[(size_t)(r + 8) * 768 + c]) =
                        __floats2bfloat162_rn((acc[mt][nt][2] + b0) * sc,
                                              (acc[mt][nt][3] + b1) * sc);
#pragma unroll
                    for (int k = 0; k < 4; k++) acc[mt][nt][k] = 0.f;
                }
            }
        }
    }
}

// ---------------------------------------------------------------------------
// GEMM1 (f16 x f16 -> f16 accum PROBE; persistent over N, 3-stage B pipeline):
// out[M,256] = h[M,256] x Wproj + bproj + x  (fp32 out)
// 128-row M-tiles (grid 1024). acc in f16x2 (32 regs) frees registers for the
// kb==2 residual preload (32 float regs) -> DRAM latency covered by real work.
// smem: A 65536 + 3 x 16384 B = 114688 B  (2 CTAs/SM)
// ---------------------------------------------------------------------------
#define GEMM1_SMEM 114688

__global__ __launch_bounds__(256, 2) void gemm1_persist(const float* __restrict__ bias,
                                                        const float* __restrict__ resid,
                                                        float* __restrict__ outf) {
    extern __shared__ char smraw[];
    char* smB = smraw + 65536;

    int m0 = blockIdx.x * 128;
    int tid = threadIdx.x;
    int lane = tid & 31, warp = tid >> 5;
    int wm = warp >> 2, wn = warp & 3;   // 2 x 4 warp grid, warp tile 64x32
    int g = lane >> 2, t = lane & 3;

    int arow = lane & 15;
    int acol = (lane >> 4) << 3;
    int brow = (lane & 7) + ((lane >> 4) << 3);
    int bcol = (lane & 8) ? 8 : 0;
    uint32_t aBase = (uint32_t)__cvta_generic_to_shared(smraw);
    uint32_t bBase0 = aBase + 65536;

    auto load_B = [&](int f, int st) {
        int it = f >> 2, kb = f & 3;
#pragma unroll
        for (int i = 0; i < 4; i++) {
            int li = tid + i * 256;
            int row = li >> 3, c16 = li & 7;
            cp_async16(smB + st * 16384 + b_sw(row, c16),
                       &g_WprojT[(size_t)(it * 128 + row) * 256 + kb * 64 + c16 * 8]);
        }
        asm volatile("cp.async.commit_group;\n" ::: "memory");
    };

    load_B(0, 0);

    // ---- load A (once): 128 x 256 f16, swizzled rows ----
#pragma unroll
    for (int i = 0; i < 16; i++) {
        int li = tid + i * 256;
        int row = li >> 5, c16 = li & 31;
        cp_async16(smraw + a_sw(row, c16),
                   &g_h[(size_t)(m0 + row) * 256 + c16 * 8]);
    }
    asm volatile("cp.async.commit_group;\n" ::: "memory");

    load_B(1, 1);

    uint32_t acc[4][4][2];   // f16x2 accumulators
#pragma unroll
    for (int i = 0; i < 4; i++)
#pragma unroll
        for (int j = 0; j < 4; j++) { acc[i][j][0] = 0u; acc[i][j][1] = 0u; }

    float2 rx[16];   // residual preload (kb==2 -> kb==3)

    for (int f = 0; f < 8; f++) {
        int it = f >> 2, kb = f & 3;
        int st = f % 3;
        asm volatile("cp.async.wait_group 1;\n" ::: "memory");
        __syncthreads();
        if (f + 2 < 8) load_B(f + 2, (f + 2) % 3);

        if (kb == 2) {
            int n0 = it * 128;
#pragma unroll
            for (int mt = 0; mt < 4; mt++)
#pragma unroll
                for (int nt = 0; nt < 4; nt++) {
                    int r = m0 + wm * 64 + mt * 16 + g + ((nt & 1) ? 8 : 0);
                    int c = n0 + wn * 32 + ((nt >> 1) * 2 + 0) * 8;  // unused pattern guard
                    (void)c;
                }
            // preload: one float2 per (mt, nt) pair row g and row g+8 packed
#pragma unroll
            for (int mt = 0; mt < 4; mt++)
#pragma unroll
                for (int nt = 0; nt < 4; nt++) {
                    int r = m0 + wm * 64 + mt * 16 + g;
                    int c = n0 + wn * 32 + nt * 8 + t * 2;
                    rx[mt * 4 + nt] = *(const float2*)(resid + (size_t)r * 256 + c);
                }
        }

        uint32_t bB = bBase0 + st * 16384;

#pragma unroll
        for (int ks = 0; ks < 4; ks++) {
            int c16a = (kb * 64 + ks * 16 + acol) >> 3;
            int c16b = (ks * 16 + bcol) >> 3;
            uint32_t af[4][4], bfr[4][2];
#pragma unroll
            for (int mt = 0; mt < 4; mt++) {
                int r = wm * 64 + mt * 16 + arow;
                ldsm_x4(af[mt], aBase + a_sw(r, c16a));
            }
#pragma unroll
            for (int p = 0; p < 2; p++) {
                int r = wn * 32 + p * 16 + brow;
                uint32_t r4[4];
                ldsm_x4(r4, bB + b_sw(r, c16b));
                bfr[2 * p][0] = r4[0]; bfr[2 * p][1] = r4[1];
                bfr[2 * p + 1][0] = r4[2]; bfr[2 * p + 1][1] = r4[3];
            }
#pragma unroll
            for (int mt = 0; mt < 4; mt++)
#pragma unroll
                for (int nt = 0; nt < 4; nt++)
                    mma_f16acc(acc[mt][nt], af[mt], bfr[nt]);
        }

        if (kb == 3) {
            int n0 = it * 128;
#pragma unroll
            for (int mt = 0; mt < 4; mt++) {
                int r = m0 + wm * 64 + mt * 16 + g;
#pragma unroll
                for (int nt = 0; nt < 4; nt++) {
                    int c = n0 + wn * 32 + nt * 8 + t * 2;
                    float b0 = bias[c], b1 = bias[c + 1];
                    __half2 h0 = *reinterpret_cast<__half2*>(&acc[mt][nt][0]); // row g
                    __half2 h1 = *reinterpret_cast<__half2*>(&acc[mt][nt][1]); // row g+8
                    float2 rx0 = rx[mt * 4 + nt];
                    size_t i0 = (size_t)r * 256 + c;
                    float2 o0;
                    o0.x = __low2float(h0) + b0 + rx0.x;
                    o0.y = __high2float(h0) + b1 + rx0.y;
                    *(float2*)(outf + i0) = o0;
                    // row g+8 residual loaded here (L2-hot: same lines as neighbors)
                    size_t i1 = (size_t)(r + 8) * 256 + c;
                    float2 rx1 = *(const float2*)(resid + i1);
                    float2 o1;
                    o1.x = __low2float(h1) + b0 + rx1.x;
                    o1.y = __high2float(h1) + b1 + rx1.y;
                    *(float2*)(outf + i1) = o1;
                    acc[mt][nt][0] = 0u; acc[mt][nt][1] = 0u;
                }
            }
        }
    }
}

// ---------------------------------------------------------------------------
// Stripe attention (R10 state; h written as f16 for gemm1's f16 mma).
// smem: sQ [256][40] (reused as sO), sK [256][40], sVt [32][264] = 57856 B
// ---------------------------------------------------------------------------
#define ATTN_SMEM 57856

__global__ __launch_bounds__(256, 2) void attn_kernel() {
    extern __shared__ __nv_bfloat16 smA[];
    __nv_bfloat16* sQ  = smA;                    // [256][40]  (reused as sO)
    __nv_bfloat16* sK  = smA + 10240;            // [256][40]
    __nv_bfloat16* sVt = smA + 20480;            // [32][264]  (V transposed)
    __half*        sO  = (__half*)sQ;            // staged output (f16)

    int bid = blockIdx.x;
    int head   = bid & 3;
    int grp    = (bid >> 2) & 63;
    int b      = (bid >> 8) & 7;
    int branch = bid >> 11;                       // 0 = horizontal, 1 = vertical
    int off = branch << 7;                        // 0 or 128
    int chq = off + head * 32;

    int tid = threadIdx.x;
    int lane = tid & 31, warp = tid >> 5;

    {
        int s = tid;  // seq position 0..255
        size_t tok;
        if (branch == 0)
            tok = (size_t)(b * 128 + grp * 2) * 128 + s;
        else
            tok = (size_t)(b * 128 + (s & 127)) * 128 + grp * 2 + (s >> 7);
        const __nv_bfloat16* base = g_qkv + tok * 768;
#pragma unroll
        for (int i = 0; i < 4; i++)
            *(uint4*)&sQ[s * 40 + i * 8] = *(const uint4*)&base[chq + i * 8];
#pragma unroll
        for (int i = 0; i < 4; i++)
            *(uint4*)&sK[s * 40 + i * 8] = *(const uint4*)&base[256 + chq + i * 8];
        __nv_bfloat16 vv[32];
#pragma unroll
        for (int i = 0; i < 4; i++)
            *(uint4*)&vv[i * 8] = *(const uint4*)&base[512 + chq + i * 8];
#pragma unroll
        for (int d = 0; d < 32; d++)
            sVt[d * 264 + s] = vv[d];
    }
    __syncthreads();

    int g = lane >> 2, t = lane & 3;
    int mbase = warp * 32;

    int arow = lane & 15;
    int acol = (lane >> 4) << 3;
    int brow = (lane & 7) + ((lane >> 4) << 3);
    int bcol = (lane & 8) ? 8 : 0;
    uint32_t qBase = (uint32_t)__cvta_generic_to_shared(sQ);
    uint32_t kBase = (uint32_t)__cvta_generic_to_shared(sK);
    uint32_t vBase = (uint32_t)__cvta_generic_to_shared(sVt);

    uint32_t qa[2][2][4];
#pragma unroll
    for (int mt = 0; mt < 2; mt++)
#pragma unroll
        for (int ks = 0; ks < 2; ks++)
            ldsm_x4(qa[mt][ks],
                    qBase + ((mbase + mt * 16 + arow) * 40 + ks * 16 + acol) * 2);

    float o[2][4][4];
#pragma unroll
    for (int i = 0; i < 2; i++)
#pragma unroll
        for (int j = 0; j < 4; j++)
#pragma unroll
            for (int k = 0; k < 4; k++) o[i][j][k] = 0.f;
    float lrow[2][2] = {{0.f, 0.f}, {0.f, 0.f}};

#pragma unroll
    for (int kc = 0; kc < 8; kc++) {
        float sacc[2][4][4];
#pragma unroll
        for (int i = 0; i < 2; i++)
#pragma unroll
            for (int j = 0; j < 4; j++)
#pragma unroll
                for (int k = 0; k < 4; k++) sacc[i][j][k] = 0.f;

#pragma unroll
        for (int ks = 0; ks < 2; ks++) {
            uint32_t kb[4][2];
#pragma unroll
            for (int p = 0; p < 2; p++) {
                uint32_t r4[4];
                ldsm_x4(r4, kBase + ((kc * 32 + p * 16 + brow) * 40 + ks * 16 + bcol) * 2);
                kb[2 * p][0] = r4[0]; kb[2 * p][1] = r4[1];
                kb[2 * p + 1][0] = r4[2]; kb[2 * p + 1][1] = r4[3];
            }
#pragma unroll
            for (int mt = 0; mt < 2; mt++)
#pragma unroll
                for (int nt = 0; nt < 4; nt++)
                    mma_bf16(sacc[mt][nt], qa[mt][ks], kb[nt]);
        }

        // P = exp2(S) via MUFU
#pragma unroll
        for (int mt = 0; mt < 2; mt++)
#pragma unroll
            for (int hi = 0; hi < 2; hi++) {
                float rs = 0.f;
#pragma unroll
                for (int nt = 0; nt < 4; nt++) {
                    float p0 = ex2_fast(sacc[mt][nt][hi * 2]);
                    float p1 = ex2_fast(sacc[mt][nt][hi * 2 + 1]);
                    sacc[mt][nt][hi * 2] = p0;
                    sacc[mt][nt][hi * 2 + 1] = p1;
                    rs += p0 + p1;
                }
                lrow[mt][hi] += rs;
            }

        // O += P V
#pragma unroll
        for (int ksv = 0; ksv < 2; ksv++) {
            uint32_t pa[2][4];
#pragma unroll
            for (int mt = 0; mt < 2; mt++) {
                pa[mt][0] = pack_bf(sacc[mt][2 * ksv][0], sacc[mt][2 * ksv][1]);
                pa[mt][1] = pack_bf(sacc[mt][2 * ksv][2], sacc[mt][2 * ksv][3]);
                pa[mt][2] = pack_bf(sacc[mt][2 * ksv + 1][0], sacc[mt][2 * ksv + 1][1]);
                pa[mt][3] = pack_bf(sacc[mt][2 * ksv + 1][2], sacc[mt][2 * ksv + 1][3]);
            }
            uint32_t vb[4][2];
            int kkv = kc * 32 + ksv * 16;
#pragma unroll
            for (int p = 0; p < 2; p++) {
                uint32_t r4[4];
                ldsm_x4(r4, vBase + ((p * 16 + brow) * 264 + kkv + bcol) * 2);
                vb[2 * p][0] = r4[0]; vb[2 * p][1] = r4[1];
                vb[2 * p + 1][0] = r4[2]; vb[2 * p + 1][1] = r4[3];
            }
#pragma unroll
            for (int mt = 0; mt < 2; mt++)
#pragma unroll
                for (int nt = 0; nt < 4; nt++)
                    mma_bf16(o[mt][nt], pa[mt], vb[nt]);
        }
    }

    // final row-sum reduce, normalize, stage to smem as f16
#pragma unroll
    for (int mt = 0; mt < 2; mt++)
#pragma unroll
        for (int hi = 0; hi < 2; hi++) {
            float l = lrow[mt][hi];
            l += __shfl_xor_sync(0xffffffffu, l, 1);
            l += __shfl_xor_sync(0xffffffffu, l, 2);
            float inv = 1.0f / l;
            int r = mbase + mt * 16 + g + hi * 8;
#pragma unroll
            for (int nt = 0; nt < 4; nt++) {
                *reinterpret_cast<__half2*>(&sO[r * 40 + nt * 8 + t * 2]) =
                    __floats2half2_rn(o[mt][nt][hi * 2] * inv, o[mt][nt][hi * 2 + 1] * inv);
            }
        }
    __syncthreads();

    // cooperative coalesced write to g_h (f16 bits)
#pragma unroll
    for (int i = 0; i < 4; i++) {
        int li = i * 256 + tid;
        int s = li >> 2, seg = li & 3;
        size_t tok;
        if (branch == 0)
            tok = (size_t)(b * 128 + grp * 2) * 128 + s;
        else
            tok = (size_t)(b * 128 + (s & 127)) * 128 + grp * 2 + (s >> 7);
        *(uint4*)&g_h[tok * 256 + chq + seg * 8] = *(const uint4*)&sO[s * 40 + seg * 8];
    }
}

// ---------------------------------------------------------------------------
// launch
// ---------------------------------------------------------------------------
extern "C" void kernel_launch(void* const* d_in, const int* in_sizes, int n_in,
                              void* d_out, int out_size) {
    const float* x     = (const float*)d_in[0];
    const float* Wqkv  = (const float*)d_in[1];
    const float* bqkv  = (const float*)d_in[2];
    const float* Wproj = (const float*)d_in[3];
    const float* bproj = (const float*)d_in[4];
    const float* gamma = (const float*)d_in[5];
    const float* beta  = (const float*)d_in[6];
    float* out = (float*)d_out;

    cudaFuncSetAttribute(gemm0_persist, cudaFuncAttributeMaxDynamicSharedMemorySize, GEMM0_SMEM);
    cudaFuncSetAttribute(gemm1_persist, cudaFuncAttributeMaxDynamicSharedMemorySize, GEMM1_SMEM);
    cudaFuncSetAttribute(attn_kernel, cudaFuncAttributeMaxDynamicSharedMemorySize, ATTN_SMEM);

    prep_weights<<<768, 256>>>(Wqkv, Wproj);
    gemm0_persist<<<TOKENS / 128, 256, GEMM0_SMEM>>>(x, gamma, beta, bqkv);
    attn_kernel<<<4096, 256, ATTN_SMEM>>>();
    gemm1_persist<<<TOKENS / 128, 256, GEMM1_SMEM>>>(bproj, x, out);
}

// round 14
// speedup vs baseline: 1.0139x; 1.0139x over previous
#include <cuda_runtime.h>
#include <cuda_bf16.h>
#include <cuda_fp16.h>
#include <cstdint>

#define TOKENS 131072            // 8 * 128 * 128
#define DIM 256

// scale * log2(e) folded into Q at GEMM0 epilogue
#define K2SCALE 0.25503837897544077f

// ---------------------------------------------------------------------------
// Scratch (device globals — no cudaMalloc allowed)
// ---------------------------------------------------------------------------
__device__ __nv_bfloat16 g_qkv[(size_t)TOKENS * 3 * DIM];     // 192 MiB (bf16)
__device__ __half g_h[(size_t)TOKENS * DIM];                  //  64 MiB (f16)
__device__ __nv_bfloat16 g_WqkvT[3 * DIM * DIM];              // [768][256] bf16
__device__ __half g_WprojT[DIM * DIM];                        // [256][256] f16

// ---------------------------------------------------------------------------
// PTX helpers
// ---------------------------------------------------------------------------
__device__ __forceinline__ void mma_bf16(float* c, const uint32_t* a, const uint32_t* b) {
    asm("mma.sync.aligned.m16n8k16.row.col.f32.bf16.bf16.f32 "
        "{%0,%1,%2,%3}, {%4,%5,%6,%7}, {%8,%9}, {%0,%1,%2,%3};\n"
        : "+f"(c[0]), "+f"(c[1]), "+f"(c[2]), "+f"(c[3])
        : "r"(a[0]), "r"(a[1]), "r"(a[2]), "r"(a[3]), "r"(b[0]), "r"(b[1]));
}

// f16 x f16 -> f16 accumulate (rate-equal, but halves accumulator registers)
__device__ __forceinline__ void mma_f16acc(uint32_t* c, const uint32_t* a, const uint32_t* b) {
    asm("mma.sync.aligned.m16n8k16.row.col.f16.f16.f16.f16 "
        "{%0,%1}, {%2,%3,%4,%5}, {%6,%7}, {%0,%1};\n"
        : "+r"(c[0]), "+r"(c[1])
        : "r"(a[0]), "r"(a[1]), "r"(a[2]), "r"(a[3]), "r"(b[0]), "r"(b[1]));
}

__device__ __forceinline__ void ldsm_x4(uint32_t* r, uint32_t addr) {
    asm volatile("ldmatrix.sync.aligned.m8n8.x4.shared.b16 {%0,%1,%2,%3}, [%4];"
                 : "=r"(r[0]), "=r"(r[1]), "=r"(r[2]), "=r"(r[3]) : "r"(addr));
}

__device__ __forceinline__ void cp_async16(void* smem_ptr, const void* gmem_ptr) {
    uint32_t s = (uint32_t)__cvta_generic_to_shared(smem_ptr);
    asm volatile("cp.async.cg.shared.global [%0], [%1], 16;\n" :: "r"(s), "l"(gmem_ptr));
}

__device__ __forceinline__ uint32_t pack_bf(float x, float y) {
    __nv_bfloat162 h = __floats2bfloat162_rn(x, y);
    return *reinterpret_cast<uint32_t*>(&h);
}

__device__ __forceinline__ float ex2_fast(float x) {
    float y;
    asm("ex2.approx.f32 %0, %1;" : "=f"(y) : "f"(x));
    return y;
}

// swizzled chunk offsets. A rows = 512B (32 chunks); B rows = 128B (8 chunks).
__device__ __forceinline__ uint32_t a_sw(int row, int c16) {   // bytes
    return (uint32_t)(row * 512 + ((c16 ^ (row & 7)) << 4));
}
__device__ __forceinline__ uint32_t b_sw(int row, int c16) {   // bytes
    return (uint32_t)(row * 128 + ((c16 ^ (row & 7)) << 4));
}

// ---------------------------------------------------------------------------
// Weight prep: Wqkv -> bf16 transpose; Wproj -> f16 transpose (tiny)
// ---------------------------------------------------------------------------
__global__ void prep_weights(const float* __restrict__ Wqkv, const float* __restrict__ Wproj) {
    int n = blockIdx.x;        // 0..767
    int k = threadIdx.x;       // 0..255
    g_WqkvT[n * DIM + k] = __float2bfloat16(Wqkv[(size_t)k * 768 + n]);
    if (n < DIM)
        g_WprojT[n * DIM + k] = __float2half(Wproj[(size_t)k * DIM + n]);
}

// ---------------------------------------------------------------------------
// GEMM0 (bf16, persistent over N, LN fused, 3-stage B pipeline) — R10 state.
// qkv[M,768] = LN(x)[M,256] x Wqkv (+bqkv).
// smem total: 65536 + 49152 = 114688 B  (2 CTAs/SM)
// ---------------------------------------------------------------------------
#define GEMM0_SMEM 114688

__global__ __launch_bounds__(256, 2) void gemm0_persist(const float* __restrict__ x,
                                                        const float* __restrict__ gamma,
                                                        const float* __restrict__ beta,
                                                        const float* __restrict__ bias) {
    extern __shared__ char smraw[];
    __nv_bfloat16* smA = (__nv_bfloat16*)smraw;            // A: [0, 65536) bytes
    char* smB = smraw + 65536;                             // B stage s at s*16384

    int m0 = blockIdx.x * 128;
    int tid = threadIdx.x;
    int lane = tid & 31, warp = tid >> 5;
    int wm = warp >> 2, wn = warp & 3;   // 2 x 4 warp grid
    int g = lane >> 2, t = lane & 3;

    int arow = lane & 15;
    int acol = (lane >> 4) << 3;
    int brow = (lane & 7) + ((lane >> 4) << 3);
    int bcol = (lane & 8) ? 8 : 0;
    uint32_t aBase = (uint32_t)__cvta_generic_to_shared(smraw);
    uint32_t bBase0 = aBase + 65536;

    auto load_B = [&](int f, int st) {     // f -> (it, kb)
        int it = f >> 2, kb = f & 3;
#pragma unroll
        for (int i = 0; i < 4; i++) {
            int li = tid + i * 256;           // 0..1023
            int row = li >> 3, c16 = li & 7;  // 128 rows x 8 chunks
            cp_async16(smB + st * 16384 + b_sw(row, c16),
                       &g_WqkvT[(size_t)(it * 128 + row) * 256 + kb * 64 + c16 * 8]);
        }
        asm volatile("cp.async.commit_group;\n" ::: "memory");
    };

    load_B(0, 0);
    load_B(1, 1);

    // ---- LN prologue: 8 warps x 16 rows, write swizzled bf16 A tile ----
    {
        int c0 = lane * 8;                   // chunk index = lane
        float4 ga = *(const float4*)(gamma + c0);
        float4 gb = *(const float4*)(gamma + c0 + 4);
        float4 ba = *(const float4*)(beta + c0);
        float4 bb = *(const float4*)(beta + c0 + 4);
        float gg[8] = {ga.x, ga.y, ga.z, ga.w, gb.x, gb.y, gb.z, gb.w};
        float be[8] = {ba.x, ba.y, ba.z, ba.w, bb.x, bb.y, bb.z, bb.w};
#pragma unroll 4
        for (int i = 0; i < 16; i++) {
            int row = warp * 16 + i;
            const float* xr = x + (size_t)(m0 + row) * 256 + c0;
            float4 v0 = *(const float4*)xr;
            float4 v1 = *(const float4*)(xr + 4);
            float v[8] = {v0.x, v0.y, v0.z, v0.w, v1.x, v1.y, v1.z, v1.w};
            float s = 0.f, sq = 0.f;
#pragma unroll
            for (int j = 0; j < 8; j++) { s += v[j]; sq += v[j] * v[j]; }
#pragma unroll
            for (int o = 16; o > 0; o >>= 1) {
                s  += __shfl_xor_sync(0xffffffffu, s, o);
                sq += __shfl_xor_sync(0xffffffffu, sq, o);
            }
            float mean = s * (1.0f / DIM);
            float var  = sq * (1.0f / DIM) - mean * mean;
            float rstd = rsqrtf(var + 1e-5f);
            __nv_bfloat16 y[8];
#pragma unroll
            for (int j = 0; j < 8; j++)
                y[j] = __float2bfloat16((v[j] - mean) * rstd * gg[j] + be[j]);
            *(uint4*)((char*)smA + a_sw(row, lane)) = *(uint4*)y;
        }
    }

    float acc[4][4][4];
#pragma unroll
    for (int i = 0; i < 4; i++)
#pragma unroll
        for (int j = 0; j < 4; j++)
#pragma unroll
            for (int k = 0; k < 4; k++) acc[i][j][k] = 0.f;

    for (int f = 0; f < 24; f++) {
        int it = f >> 2, kb = f & 3;
        int st = f % 3;
        asm volatile("cp.async.wait_group 1;\n" ::: "memory");
        __syncthreads();
        if (f + 2 < 24) load_B(f + 2, (f + 2) % 3);

        uint32_t bB = bBase0 + st * 16384;

#pragma unroll
        for (int ks = 0; ks < 4; ks++) {
            int c16a = (kb * 64 + ks * 16 + acol) >> 3;
            int c16b = (ks * 16 + bcol) >> 3;
            uint32_t af[4][4], bfr[4][2];
#pragma unroll
            for (int mt = 0; mt < 4; mt++) {
                int r = wm * 64 + mt * 16 + arow;
                ldsm_x4(af[mt], aBase + a_sw(r, c16a));
            }
#pragma unroll
            for (int p = 0; p < 2; p++) {
                int r = wn * 32 + p * 16 + brow;
                uint32_t r4[4];
                ldsm_x4(r4, bB + b_sw(r, c16b));
                bfr[2 * p][0] = r4[0]; bfr[2 * p][1] = r4[1];
                bfr[2 * p + 1][0] = r4[2]; bfr[2 * p + 1][1] = r4[3];
            }
#pragma unroll
            for (int mt = 0; mt < 4; mt++)
#pragma unroll
                for (int nt = 0; nt < 4; nt++)
                    mma_bf16(acc[mt][nt], af[mt], bfr[nt]);
        }

        if (kb == 3) {
            int n0 = it * 128;
            float sc = (it < 2) ? K2SCALE : 1.0f;   // Q scaled; K, V plain
#pragma unroll
            for (int mt = 0; mt < 4; mt++) {
                int r = m0 + wm * 64 + mt * 16 + g;
#pragma unroll
                for (int nt = 0; nt < 4; nt++) {
                    int c = n0 + wn * 32 + nt * 8 + t * 2;
                    float b0 = bias[c], b1 = bias[c + 1];
                    *reinterpret_cast<__nv_bfloat162*>(&g_qkv[(size_t)r * 768 + c]) =
                        __floats2bfloat162_rn((acc[mt][nt][0] + b0) * sc,
                                              (acc[mt][nt][1] + b1) * sc);
                    *reinterpret_cast<__nv_bfloat162*>(&g_qkv[(size_t)(r + 8) * 768 + c]) =
                        __floats2bfloat162_rn((acc[mt][nt][2] + b0) * sc,
                                              (acc[mt][nt][3] + b1) * sc);
#pragma unroll
                    for (int k = 0; k < 4; k++) acc[mt][nt][k] = 0.f;
                }
            }
        }
    }
}

// ---------------------------------------------------------------------------
// GEMM1 (f16 x f16 -> f16 accum; 64-row M-tiles; 3 CTAs/SM):
// out[M,256] = h[M,256] x Wproj + bproj + x  (fp32 out)
// grid = 2048 CTAs. __launch_bounds__(256,3) caps regs at 85 -> 24 warps/SM
// (+50% latency-hiding). acc f16x2 = 16 regs; warp tile 32x32.
// smem: A 64x512B swizzled = 32768 + 2 x 16384 B = 65536 B  (3 CTAs/SM)
// ---------------------------------------------------------------------------
#define GEMM1_SMEM 65536

__global__ __launch_bounds__(256, 3) void gemm1_persist(const float* __restrict__ bias,
                                                        const float* __restrict__ resid,
                                                        float* __restrict__ outf) {
    extern __shared__ char smraw[];
    char* smB = smraw + 32768;

    int m0 = blockIdx.x * 64;
    int tid = threadIdx.x;
    int lane = tid & 31, warp = tid >> 5;
    int wm = warp >> 2, wn = warp & 3;   // 2 x 4 warp grid, warp tile 32x32
    int g = lane >> 2, t = lane & 3;

    int arow = lane & 15;
    int acol = (lane >> 4) << 3;
    int brow = (lane & 7) + ((lane >> 4) << 3);
    int bcol = (lane & 8) ? 8 : 0;
    uint32_t aBase = (uint32_t)__cvta_generic_to_shared(smraw);
    uint32_t bBase0 = aBase + 32768;

    auto load_B = [&](int f, int st) {
        int it = f >> 2, kb = f & 3;
#pragma unroll
        for (int i = 0; i < 4; i++) {
            int li = tid + i * 256;
            int row = li >> 3, c16 = li & 7;
            cp_async16(smB + st * 16384 + b_sw(row, c16),
                       &g_WprojT[(size_t)(it * 128 + row) * 256 + kb * 64 + c16 * 8]);
        }
        asm volatile("cp.async.commit_group;\n" ::: "memory");
    };

    load_B(0, 0);

    // ---- load A (once): 64 x 256 f16, swizzled rows ----
#pragma unroll
    for (int i = 0; i < 8; i++) {
        int li = tid + i * 256;            // 0..2047
        int row = li >> 5, c16 = li & 31;
        cp_async16(smraw + a_sw(row, c16),
                   &g_h[(size_t)(m0 + row) * 256 + c16 * 8]);
    }
    asm volatile("cp.async.commit_group;\n" ::: "memory");

    uint32_t acc[2][4][2];   // f16x2 accumulators (16 regs)
#pragma unroll
    for (int i = 0; i < 2; i++)
#pragma unroll
        for (int j = 0; j < 4; j++) { acc[i][j][0] = 0u; acc[i][j][1] = 0u; }

    for (int f = 0; f < 8; f++) {
        int it = f >> 2, kb = f & 3, st = f & 1;
        asm volatile("cp.async.wait_group 0;\n" ::: "memory");
        __syncthreads();
        if (f + 1 < 8) load_B(f + 1, (f + 1) & 1);

        uint32_t bB = bBase0 + st * 16384;

#pragma unroll
        for (int ks = 0; ks < 4; ks++) {
            int c16a = (kb * 64 + ks * 16 + acol) >> 3;
            int c16b = (ks * 16 + bcol) >> 3;
            uint32_t af[2][4], bfr[4][2];
#pragma unroll
            for (int mt = 0; mt < 2; mt++) {
                int r = wm * 32 + mt * 16 + arow;
                ldsm_x4(af[mt], aBase + a_sw(r, c16a));
            }
#pragma unroll
            for (int p = 0; p < 2; p++) {
                int r = wn * 32 + p * 16 + brow;
                uint32_t r4[4];
                ldsm_x4(r4, bB + b_sw(r, c16b));
                bfr[2 * p][0] = r4[0]; bfr[2 * p][1] = r4[1];
                bfr[2 * p + 1][0] = r4[2]; bfr[2 * p + 1][1] = r4[3];
            }
#pragma unroll
            for (int mt = 0; mt < 2; mt++)
#pragma unroll
                for (int nt = 0; nt < 4; nt++)
                    mma_f16acc(acc[mt][nt], af[mt], bfr[nt]);
        }

        if (kb == 3) {
            int n0 = it * 128;
#pragma unroll
            for (int mt = 0; mt < 2; mt++) {
                int r = m0 + wm * 32 + mt * 16 + g;
#pragma unroll
                for (int nt = 0; nt < 4; nt++) {
                    int c = n0 + wn * 32 + nt * 8 + t * 2;
                    float b0 = bias[c], b1 = bias[c + 1];
                    __half2 h0 = *reinterpret_cast<__half2*>(&acc[mt][nt][0]); // row r
                    __half2 h1 = *reinterpret_cast<__half2*>(&acc[mt][nt][1]); // row r+8
                    size_t i0 = (size_t)r * 256 + c;
                    float2 rx0 = *(const float2*)(resid + i0);
                    float2 o0;
                    o0.x = __low2float(h0) + b0 + rx0.x;
                    o0.y = __high2float(h0) + b1 + rx0.y;
                    *(float2*)(outf + i0) = o0;
                    size_t i1 = (size_t)(r + 8) * 256 + c;
                    float2 rx1 = *(const float2*)(resid + i1);
                    float2 o1;
                    o1.x = __low2float(h1) + b0 + rx1.x;
                    o1.y = __high2float(h1) + b1 + rx1.y;
                    *(float2*)(outf + i1) = o1;
                    acc[mt][nt][0] = 0u; acc[mt][nt][1] = 0u;
                }
            }
        }
    }
}

// ---------------------------------------------------------------------------
// Stripe attention (R10 state; output staged/written as f16 for gemm1).
// smem: sQ [256][40] (reused as sO), sK [256][40], sVt [32][264] = 57856 B
// ---------------------------------------------------------------------------
#define ATTN_SMEM 57856

__global__ __launch_bounds__(256, 2) void attn_kernel() {
    extern __shared__ __nv_bfloat16 smA[];
    __nv_bfloat16* sQ  = smA;                    // [256][40]  (reused as sO)
    __nv_bfloat16* sK  = smA + 10240;            // [256][40]
    __nv_bfloat16* sVt = smA + 20480;            // [32][264]  (V transposed)
    __half*        sO  = (__half*)sQ;            // staged output (f16)

    int bid = blockIdx.x;
    int head   = bid & 3;
    int grp    = (bid >> 2) & 63;
    int b      = (bid >> 8) & 7;
    int branch = bid >> 11;                       // 0 = horizontal, 1 = vertical
    int off = branch << 7;                        // 0 or 128
    int chq = off + head * 32;

    int tid = threadIdx.x;
    int lane = tid & 31, warp = tid >> 5;

    {
        int s = tid;  // seq position 0..255
        size_t tok;
        if (branch == 0)
            tok = (size_t)(b * 128 + grp * 2) * 128 + s;
        else
            tok = (size_t)(b * 128 + (s & 127)) * 128 + grp * 2 + (s >> 7);
        const __nv_bfloat16* base = g_qkv + tok * 768;
#pragma unroll
        for (int i = 0; i < 4; i++)
            *(uint4*)&sQ[s * 40 + i * 8] = *(const uint4*)&base[chq + i * 8];
#pragma unroll
        for (int i = 0; i < 4; i++)
            *(uint4*)&sK[s * 40 + i * 8] = *(const uint4*)&base[256 + chq + i * 8];
        __nv_bfloat16 vv[32];
#pragma unroll
        for (int i = 0; i < 4; i++)
            *(uint4*)&vv[i * 8] = *(const uint4*)&base[512 + chq + i * 8];
#pragma unroll
        for (int d = 0; d < 32; d++)
            sVt[d * 264 + s] = vv[d];
    }
    __syncthreads();

    int g = lane >> 2, t = lane & 3;
    int mbase = warp * 32;

    int arow = lane & 15;
    int acol = (lane >> 4) << 3;
    int brow = (lane & 7) + ((lane >> 4) << 3);
    int bcol = (lane & 8) ? 8 : 0;
    uint32_t qBase = (uint32_t)__cvta_generic_to_shared(sQ);
    uint32_t kBase = (uint32_t)__cvta_generic_to_shared(sK);
    uint32_t vBase = (uint32_t)__cvta_generic_to_shared(sVt);

    uint32_t qa[2][2][4];
#pragma unroll
    for (int mt = 0; mt < 2; mt++)
#pragma unroll
        for (int ks = 0; ks < 2; ks++)
            ldsm_x4(qa[mt][ks],
                    qBase + ((mbase + mt * 16 + arow) * 40 + ks * 16 + acol) * 2);

    float o[2][4][4];
#pragma unroll
    for (int i = 0; i < 2; i++)
#pragma unroll
        for (int j = 0; j < 4; j++)
#pragma unroll
            for (int k = 0; k < 4; k++) o[i][j][k] = 0.f;
    float lrow[2][2] = {{0.f, 0.f}, {0.f, 0.f}};

#pragma unroll
    for (int kc = 0; kc < 8; kc++) {
        float sacc[2][4][4];
#pragma unroll
        for (int i = 0; i < 2; i++)
#pragma unroll
            for (int j = 0; j < 4; j++)
#pragma unroll
                for (int k = 0; k < 4; k++) sacc[i][j][k] = 0.f;

#pragma unroll
        for (int ks = 0; ks < 2; ks++) {
            uint32_t kb[4][2];
#pragma unroll
            for (int p = 0; p < 2; p++) {
                uint32_t r4[4];
                ldsm_x4(r4, kBase + ((kc * 32 + p * 16 + brow) * 40 + ks * 16 + bcol) * 2);
                kb[2 * p][0] = r4[0]; kb[2 * p][1] = r4[1];
                kb[2 * p + 1][0] = r4[2]; kb[2 * p + 1][1] = r4[3];
            }
#pragma unroll
            for (int mt = 0; mt < 2; mt++)
#pragma unroll
                for (int nt = 0; nt < 4; nt++)
                    mma_bf16(sacc[mt][nt], qa[mt][ks], kb[nt]);
        }

        // P = exp2(S) via MUFU
#pragma unroll
        for (int mt = 0; mt < 2; mt++)
#pragma unroll
            for (int hi = 0; hi < 2; hi++) {
                float rs = 0.f;
#pragma unroll
                for (int nt = 0; nt < 4; nt++) {
                    float p0 = ex2_fast(sacc[mt][nt][hi * 2]);
                    float p1 = ex2_fast(sacc[mt][nt][hi * 2 + 1]);
                    sacc[mt][nt][hi * 2] = p0;
                    sacc[mt][nt][hi * 2 + 1] = p1;
                    rs += p0 + p1;
                }
                lrow[mt][hi] += rs;
            }

        // O += P V
#pragma unroll
        for (int ksv = 0; ksv < 2; ksv++) {
            uint32_t pa[2][4];
#pragma unroll
            for (int mt = 0; mt < 2; mt++) {
                pa[mt][0] = pack_bf(sacc[mt][2 * ksv][0], sacc[mt][2 * ksv][1]);
                pa[mt][1] = pack_bf(sacc[mt][2 * ksv][2], sacc[mt][2 * ksv][3]);
                pa[mt][2] = pack_bf(sacc[mt][2 * ksv + 1][0], sacc[mt][2 * ksv + 1][1]);
                pa[mt][3] = pack_bf(sacc[mt][2 * ksv + 1][2], sacc[mt][2 * ksv + 1][3]);
            }
            uint32_t vb[4][2];
            int kkv = kc * 32 + ksv * 16;
#pragma unroll
            for (int p = 0; p < 2; p++) {
                uint32_t r4[4];
                ldsm_x4(r4, vBase + ((p * 16 + brow) * 264 + kkv + bcol) * 2);
                vb[2 * p][0] = r4[0]; vb[2 * p][1] = r4[1];
                vb[2 * p + 1][0] = r4[2]; vb[2 * p + 1][1] = r4[3];
            }
#pragma unroll
            for (int mt = 0; mt < 2; mt++)
#pragma unroll
                for (int nt = 0; nt < 4; nt++)
                    mma_bf16(o[mt][nt], pa[mt], vb[nt]);
        }
    }

    // final row-sum reduce, normalize, stage to smem as f16
#pragma unroll
    for (int mt = 0; mt < 2; mt++)
#pragma unroll
        for (int hi = 0; hi < 2; hi++) {
            float l = lrow[mt][hi];
            l += __shfl_xor_sync(0xffffffffu, l, 1);
            l += __shfl_xor_sync(0xffffffffu, l, 2);
            float inv = 1.0f / l;
            int r = mbase + mt * 16 + g + hi * 8;
#pragma unroll
            for (int nt = 0; nt < 4; nt++) {
                *reinterpret_cast<__half2*>(&sO[r * 40 + nt * 8 + t * 2]) =
                    __floats2half2_rn(o[mt][nt][hi * 2] * inv, o[mt][nt][hi * 2 + 1] * inv);
            }
        }
    __syncthreads();

    // cooperative coalesced write to g_h (f16 bits)
#pragma unroll
    for (int i = 0; i < 4; i++) {
        int li = i * 256 + tid;
        int s = li >> 2, seg = li & 3;
        size_t tok;
        if (branch == 0)
            tok = (size_t)(b * 128 + grp * 2) * 128 + s;
        else
            tok = (size_t)(b * 128 + (s & 127)) * 128 + grp * 2 + (s >> 7);
        *(uint4*)&g_h[tok * 256 + chq + seg * 8] = *(const uint4*)&sO[s * 40 + seg * 8];
    }
}

// ---------------------------------------------------------------------------
// launch
// ---------------------------------------------------------------------------
extern "C" void kernel_launch(void* const* d_in, const int* in_sizes, int n_in,
                              void* d_out, int out_size) {
    const float* x     = (const float*)d_in[0];
    const float* Wqkv  = (const float*)d_in[1];
    const float* bqkv  = (const float*)d_in[2];
    const float* Wproj = (const float*)d_in[3];
    const float* bproj = (const float*)d_in[4];
    const float* gamma = (const float*)d_in[5];
    const float* beta  = (const float*)d_in[6];
    float* out = (float*)d_out;

    cudaFuncSetAttribute(gemm0_persist, cudaFuncAttributeMaxDynamicSharedMemorySize, GEMM0_SMEM);
    cudaFuncSetAttribute(gemm1_persist, cudaFuncAttributeMaxDynamicSharedMemorySize, GEMM1_SMEM);
    cudaFuncSetAttribute(attn_kernel, cudaFuncAttributeMaxDynamicSharedMemorySize, ATTN_SMEM);

    prep_weights<<<768, 256>>>(Wqkv, Wproj);
    gemm0_persist<<<TOKENS / 128, 256, GEMM0_SMEM>>>(x, gamma, beta, bqkv);
    attn_kernel<<<4096, 256, ATTN_SMEM>>>();
    gemm1_persist<<<TOKENS / 64, 256, GEMM1_SMEM>>>(bproj, x, out);
}

// round 15
// speedup vs baseline: 1.0171x; 1.0031x over previous
#include <cuda_runtime.h>
#include <cuda_bf16.h>
#include <cuda_fp16.h>
#include <cstdint>

#define TOKENS 131072            // 8 * 128 * 128
#define DIM 256

// scale * log2(e) folded into Q at GEMM0 epilogue
#define K2SCALE 0.25503837897544077f

// ---------------------------------------------------------------------------
// Scratch (device globals — no cudaMalloc allowed)
// ---------------------------------------------------------------------------
__device__ __nv_bfloat16 g_qkv[(size_t)TOKENS * 3 * DIM];     // 192 MiB (bf16)
__device__ __half g_h[(size_t)TOKENS * DIM];                  //  64 MiB (f16)
__device__ __nv_bfloat16 g_WqkvT[3 * DIM * DIM];              // [768][256] bf16
__device__ __half g_WprojT[DIM * DIM];                        // [256][256] f16

// ---------------------------------------------------------------------------
// PTX helpers
// ---------------------------------------------------------------------------
__device__ __forceinline__ void mma_bf16(float* c, const uint32_t* a, const uint32_t* b) {
    asm("mma.sync.aligned.m16n8k16.row.col.f32.bf16.bf16.f32 "
        "{%0,%1,%2,%3}, {%4,%5,%6,%7}, {%8,%9}, {%0,%1,%2,%3};\n"
        : "+f"(c[0]), "+f"(c[1]), "+f"(c[2]), "+f"(c[3])
        : "r"(a[0]), "r"(a[1]), "r"(a[2]), "r"(a[3]), "r"(b[0]), "r"(b[1]));
}

// f16 x f16 -> f16 accumulate (rate-equal, but halves accumulator registers)
__device__ __forceinline__ void mma_f16acc(uint32_t* c, const uint32_t* a, const uint32_t* b) {
    asm("mma.sync.aligned.m16n8k16.row.col.f16.f16.f16.f16 "
        "{%0,%1}, {%2,%3,%4,%5}, {%6,%7}, {%0,%1};\n"
        : "+r"(c[0]), "+r"(c[1])
        : "r"(a[0]), "r"(a[1]), "r"(a[2]), "r"(a[3]), "r"(b[0]), "r"(b[1]));
}

__device__ __forceinline__ void ldsm_x4(uint32_t* r, uint32_t addr) {
    asm volatile("ldmatrix.sync.aligned.m8n8.x4.shared.b16 {%0,%1,%2,%3}, [%4];"
                 : "=r"(r[0]), "=r"(r[1]), "=r"(r[2]), "=r"(r[3]) : "r"(addr));
}

__device__ __forceinline__ void cp_async16(void* smem_ptr, const void* gmem_ptr) {
    uint32_t s = (uint32_t)__cvta_generic_to_shared(smem_ptr);
    asm volatile("cp.async.cg.shared.global [%0], [%1], 16;\n" :: "r"(s), "l"(gmem_ptr));
}

__device__ __forceinline__ uint32_t pack_bf(float x, float y) {
    __nv_bfloat162 h = __floats2bfloat162_rn(x, y);
    return *reinterpret_cast<uint32_t*>(&h);
}

__device__ __forceinline__ float ex2_fast(float x) {
    float y;
    asm("ex2.approx.f32 %0, %1;" : "=f"(y) : "f"(x));
    return y;
}

// swizzled chunk offsets. A rows = 512B (32 chunks); B rows = 128B (8 chunks).
__device__ __forceinline__ uint32_t a_sw(int row, int c16) {   // bytes
    return (uint32_t)(row * 512 + ((c16 ^ (row & 7)) << 4));
}
__device__ __forceinline__ uint32_t b_sw(int row, int c16) {   // bytes
    return (uint32_t)(row * 128 + ((c16 ^ (row & 7)) << 4));
}

// ---------------------------------------------------------------------------
// Weight prep: Wqkv -> bf16 transpose; Wproj -> f16 transpose (tiny)
// ---------------------------------------------------------------------------
__global__ void prep_weights(const float* __restrict__ Wqkv, const float* __restrict__ Wproj) {
    int n = blockIdx.x;        // 0..767
    int k = threadIdx.x;       // 0..255
    g_WqkvT[n * DIM + k] = __float2bfloat16(Wqkv[(size_t)k * 768 + n]);
    if (n < DIM)
        g_WprojT[n * DIM + k] = __float2half(Wproj[(size_t)k * DIM + n]);
}

// ---------------------------------------------------------------------------
// GEMM0 (bf16, persistent over N, LN fused, 3-stage B pipeline) — R10 state
// with the final-iteration wait fixed to wait_group 0.
// qkv[M,768] = LN(x)[M,256] x Wqkv (+bqkv).
// smem total: 65536 + 49152 = 114688 B  (2 CTAs/SM)
// ---------------------------------------------------------------------------
#define GEMM0_SMEM 114688

__global__ __launch_bounds__(256, 2) void gemm0_persist(const float* __restrict__ x,
                                                        const float* __restrict__ gamma,
                                                        const float* __restrict__ beta,
                                                        const float* __restrict__ bias) {
    extern __shared__ char smraw[];
    __nv_bfloat16* smA = (__nv_bfloat16*)smraw;            // A: [0, 65536) bytes
    char* smB = smraw + 65536;                             // B stage s at s*16384

    int m0 = blockIdx.x * 128;
    int tid = threadIdx.x;
    int lane = tid & 31, warp = tid >> 5;
    int wm = warp >> 2, wn = warp & 3;   // 2 x 4 warp grid
    int g = lane >> 2, t = lane & 3;

    int arow = lane & 15;
    int acol = (lane >> 4) << 3;
    int brow = (lane & 7) + ((lane >> 4) << 3);
    int bcol = (lane & 8) ? 8 : 0;
    uint32_t aBase = (uint32_t)__cvta_generic_to_shared(smraw);
    uint32_t bBase0 = aBase + 65536;

    auto load_B = [&](int f, int st) {     // f -> (it, kb)
        int it = f >> 2, kb = f & 3;
#pragma unroll
        for (int i = 0; i < 4; i++) {
            int li = tid + i * 256;           // 0..1023
            int row = li >> 3, c16 = li & 7;  // 128 rows x 8 chunks
            cp_async16(smB + st * 16384 + b_sw(row, c16),
                       &g_WqkvT[(size_t)(it * 128 + row) * 256 + kb * 64 + c16 * 8]);
        }
        asm volatile("cp.async.commit_group;\n" ::: "memory");
    };

    load_B(0, 0);
    load_B(1, 1);

    // ---- LN prologue: 8 warps x 16 rows, write swizzled bf16 A tile ----
    {
        int c0 = lane * 8;                   // chunk index = lane
        float4 ga = *(const float4*)(gamma + c0);
        float4 gb = *(const float4*)(gamma + c0 + 4);
        float4 ba = *(const float4*)(beta + c0);
        float4 bb = *(const float4*)(beta + c0 + 4);
        float gg[8] = {ga.x, ga.y, ga.z, ga.w, gb.x, gb.y, gb.z, gb.w};
        float be[8] = {ba.x, ba.y, ba.z, ba.w, bb.x, bb.y, bb.z, bb.w};
#pragma unroll 4
        for (int i = 0; i < 16; i++) {
            int row = warp * 16 + i;
            const float* xr = x + (size_t)(m0 + row) * 256 + c0;
            float4 v0 = *(const float4*)xr;
            float4 v1 = *(const float4*)(xr + 4);
            float v[8] = {v0.x, v0.y, v0.z, v0.w, v1.x, v1.y, v1.z, v1.w};
            float s = 0.f, sq = 0.f;
#pragma unroll
            for (int j = 0; j < 8; j++) { s += v[j]; sq += v[j] * v[j]; }
#pragma unroll
            for (int o = 16; o > 0; o >>= 1) {
                s  += __shfl_xor_sync(0xffffffffu, s, o);
                sq += __shfl_xor_sync(0xffffffffu, sq, o);
            }
            float mean = s * (1.0f / DIM);
            float var  = sq * (1.0f / DIM) - mean * mean;
            float rstd = rsqrtf(var + 1e-5f);
            __nv_bfloat16 y[8];
#pragma unroll
            for (int j = 0; j < 8; j++)
                y[j] = __float2bfloat16((v[j] - mean) * rstd * gg[j] + be[j]);
            *(uint4*)((char*)smA + a_sw(row, lane)) = *(uint4*)y;
        }
    }

    float acc[4][4][4];
#pragma unroll
    for (int i = 0; i < 4; i++)
#pragma unroll
        for (int j = 0; j < 4; j++)
#pragma unroll
            for (int k = 0; k < 4; k++) acc[i][j][k] = 0.f;

    for (int f = 0; f < 24; f++) {
        int it = f >> 2, kb = f & 3;
        int st = f % 3;
        if (f + 1 < 24) {
            asm volatile("cp.async.wait_group 1;\n" ::: "memory");
        } else {
            asm volatile("cp.async.wait_group 0;\n" ::: "memory");
        }
        __syncthreads();
        if (f + 2 < 24) load_B(f + 2, (f + 2) % 3);

        uint32_t bB = bBase0 + st * 16384;

#pragma unroll
        for (int ks = 0; ks < 4; ks++) {
            int c16a = (kb * 64 + ks * 16 + acol) >> 3;
            int c16b = (ks * 16 + bcol) >> 3;
            uint32_t af[4][4], bfr[4][2];
#pragma unroll
            for (int mt = 0; mt < 4; mt++) {
                int r = wm * 64 + mt * 16 + arow;
                ldsm_x4(af[mt], aBase + a_sw(r, c16a));
            }
#pragma unroll
            for (int p = 0; p < 2; p++) {
                int r = wn * 32 + p * 16 + brow;
                uint32_t r4[4];
                ldsm_x4(r4, bB + b_sw(r, c16b));
                bfr[2 * p][0] = r4[0]; bfr[2 * p][1] = r4[1];
                bfr[2 * p + 1][0] = r4[2]; bfr[2 * p + 1][1] = r4[3];
            }
#pragma unroll
            for (int mt = 0; mt < 4; mt++)
#pragma unroll
                for (int nt = 0; nt < 4; nt++)
                    mma_bf16(acc[mt][nt], af[mt], bfr[nt]);
        }

        if (kb == 3) {
            int n0 = it * 128;
            float sc = (it < 2) ? K2SCALE : 1.0f;   // Q scaled; K, V plain
#pragma unroll
            for (int mt = 0; mt < 4; mt++) {
                int r = m0 + wm * 64 + mt * 16 + g;
#pragma unroll
                for (int nt = 0; nt < 4; nt++) {
                    int c = n0 + wn * 32 + nt * 8 + t * 2;
                    float b0 = bias[c], b1 = bias[c + 1];
                    *reinterpret_cast<__nv_bfloat162*>(&g_qkv[(size_t)r * 768 + c]) =
                        __floats2bfloat162_rn((acc[mt][nt][0] + b0) * sc,
                                              (acc[mt][nt][1] + b1) * sc);
                    *reinterpret_cast<__nv_bfloat162*>(&g_qkv[(size_t)(r + 8) * 768 + c]) =
                        __floats2bfloat162_rn((acc[mt][nt][2] + b0) * sc,
                                              (acc[mt][nt][3] + b1) * sc);
#pragma unroll
                    for (int k = 0; k < 4; k++) acc[mt][nt][k] = 0.f;
                }
            }
        }
    }
}

// ---------------------------------------------------------------------------
// GEMM1 (f16 x f16 -> f16 accum; PERSISTENT grid = 444 = 148 SM x 3 CTAs):
// out[M,256] = h[M,256] x Wproj + bproj + x  (fp32 out)
// Each CTA strides over 64-row M-tiles. Next tile's A-load is issued right
// after the last mainloop read of the current A tile, overlapping the
// epilogue's residual LDGs + fp32 STGs (the longest-latency section).
// smem: A 64x512B swizzled = 32768 + 2 x 16384 B = 65536 B  (3 CTAs/SM)
// ---------------------------------------------------------------------------
#define GEMM1_SMEM 65536
#define GEMM1_GRID 444
#define GEMM1_TILES (TOKENS / 64)

__global__ __launch_bounds__(256, 3) void gemm1_persist(const float* __restrict__ bias,
                                                        const float* __restrict__ resid,
                                                        float* __restrict__ outf) {
    extern __shared__ char smraw[];
    char* smB = smraw + 32768;

    int tid = threadIdx.x;
    int lane = tid & 31, warp = tid >> 5;
    int wm = warp >> 2, wn = warp & 3;   // 2 x 4 warp grid, warp tile 32x32
    int g = lane >> 2, t = lane & 3;

    int arow = lane & 15;
    int acol = (lane >> 4) << 3;
    int brow = (lane & 7) + ((lane >> 4) << 3);
    int bcol = (lane & 8) ? 8 : 0;
    uint32_t aBase = (uint32_t)__cvta_generic_to_shared(smraw);
    uint32_t bBase0 = aBase + 32768;

    auto load_A = [&](int mb) {
        int m0 = mb * 64;
#pragma unroll
        for (int i = 0; i < 8; i++) {
            int li = tid + i * 256;            // 0..2047
            int row = li >> 5, c16 = li & 31;
            cp_async16(smraw + a_sw(row, c16),
                       &g_h[(size_t)(m0 + row) * 256 + c16 * 8]);
        }
        asm volatile("cp.async.commit_group;\n" ::: "memory");
    };

    auto load_B = [&](int f, int st) {
        int it = f >> 2, kb = f & 3;
#pragma unroll
        for (int i = 0; i < 4; i++) {
            int li = tid + i * 256;
            int row = li >> 3, c16 = li & 7;
            cp_async16(smB + st * 16384 + b_sw(row, c16),
                       &g_WprojT[(size_t)(it * 128 + row) * 256 + kb * 64 + c16 * 8]);
        }
        asm volatile("cp.async.commit_group;\n" ::: "memory");
    };

    uint32_t acc[2][4][2];   // f16x2 accumulators (16 regs)
#pragma unroll
    for (int i = 0; i < 2; i++)
#pragma unroll
        for (int j = 0; j < 4; j++) { acc[i][j][0] = 0u; acc[i][j][1] = 0u; }

    // first tile's A load
    load_A(blockIdx.x);

    for (int mb = blockIdx.x; mb < GEMM1_TILES; mb += GEMM1_GRID) {
        int m0 = mb * 64;
        load_B(0, 0);   // pending: {A (this tile), B0}

        for (int f = 0; f < 8; f++) {
            int it = f >> 2, kb = f & 3, st = f & 1;
            asm volatile("cp.async.wait_group 0;\n" ::: "memory");
            __syncthreads();
            if (f + 1 < 8) load_B(f + 1, (f + 1) & 1);

            uint32_t bB = bBase0 + st * 16384;

#pragma unroll
            for (int ks = 0; ks < 4; ks++) {
                int c16a = (kb * 64 + ks * 16 + acol) >> 3;
                int c16b = (ks * 16 + bcol) >> 3;
                uint32_t af[2][4], bfr[4][2];
#pragma unroll
                for (int mt = 0; mt < 2; mt++) {
                    int r = wm * 32 + mt * 16 + arow;
                    ldsm_x4(af[mt], aBase + a_sw(r, c16a));
                }
#pragma unroll
                for (int p = 0; p < 2; p++) {
                    int r = wn * 32 + p * 16 + brow;
                    uint32_t r4[4];
                    ldsm_x4(r4, bB + b_sw(r, c16b));
                    bfr[2 * p][0] = r4[0]; bfr[2 * p][1] = r4[1];
                    bfr[2 * p + 1][0] = r4[2]; bfr[2 * p + 1][1] = r4[3];
                }
#pragma unroll
                for (int mt = 0; mt < 2; mt++)
#pragma unroll
                    for (int nt = 0; nt < 4; nt++)
                        mma_f16acc(acc[mt][nt], af[mt], bfr[nt]);
            }

            if (f == 7) {
                // all A reads done; overlap next tile's A load with epilogue
                __syncthreads();
                if (mb + GEMM1_GRID < GEMM1_TILES) load_A(mb + GEMM1_GRID);
            }

            if (kb == 3) {
                int n0 = it * 128;
#pragma unroll
                for (int mt = 0; mt < 2; mt++) {
                    int r = m0 + wm * 32 + mt * 16 + g;
#pragma unroll
                    for (int nt = 0; nt < 4; nt++) {
                        int c = n0 + wn * 32 + nt * 8 + t * 2;
                        float b0 = bias[c], b1 = bias[c + 1];
                        __half2 h0 = *reinterpret_cast<__half2*>(&acc[mt][nt][0]); // row r
                        __half2 h1 = *reinterpret_cast<__half2*>(&acc[mt][nt][1]); // row r+8
                        size_t i0 = (size_t)r * 256 + c;
                        float2 rx0 = *(const float2*)(resid + i0);
                        float2 o0;
                        o0.x = __low2float(h0) + b0 + rx0.x;
                        o0.y = __high2float(h0) + b1 + rx0.y;
                        *(float2*)(outf + i0) = o0;
                        size_t i1 = (size_t)(r + 8) * 256 + c;
                        float2 rx1 = *(const float2*)(resid + i1);
                        float2 o1;
                        o1.x = __low2float(h1) + b0 + rx1.x;
                        o1.y = __high2float(h1) + b1 + rx1.y;
                        *(float2*)(outf + i1) = o1;
                        acc[mt][nt][0] = 0u; acc[mt][nt][1] = 0u;
                    }
                }
            }
        }
    }
}

// ---------------------------------------------------------------------------
// Stripe attention (R10 state; output staged/written as f16 for gemm1).
// smem: sQ [256][40] (reused as sO), sK [256][40], sVt [32][264] = 57856 B
// ---------------------------------------------------------------------------
#define ATTN_SMEM 57856

__global__ __launch_bounds__(256, 2) void attn_kernel() {
    extern __shared__ __nv_bfloat16 smA[];
    __nv_bfloat16* sQ  = smA;                    // [256][40]  (reused as sO)
    __nv_bfloat16* sK  = smA + 10240;            // [256][40]
    __nv_bfloat16* sVt = smA + 20480;            // [32][264]  (V transposed)
    __half*        sO  = (__half*)sQ;            // staged output (f16)

    int bid = blockIdx.x;
    int head   = bid & 3;
    int grp    = (bid >> 2) & 63;
    int b      = (bid >> 8) & 7;
    int branch = bid >> 11;                       // 0 = horizontal, 1 = vertical
    int off = branch << 7;                        // 0 or 128
    int chq = off + head * 32;

    int tid = threadIdx.x;
    int lane = tid & 31, warp = tid >> 5;

    {
        int s = tid;  // seq position 0..255
        size_t tok;
        if (branch == 0)
            tok = (size_t)(b * 128 + grp * 2) * 128 + s;
        else
            tok = (size_t)(b * 128 + (s & 127)) * 128 + grp * 2 + (s >> 7);
        const __nv_bfloat16* base = g_qkv + tok * 768;
#pragma unroll
        for (int i = 0; i < 4; i++)
            *(uint4*)&sQ[s * 40 + i * 8] = *(const uint4*)&base[chq + i * 8];
#pragma unroll
        for (int i = 0; i < 4; i++)
            *(uint4*)&sK[s * 40 + i * 8] = *(const uint4*)&base[256 + chq + i * 8];
        __nv_bfloat16 vv[32];
#pragma unroll
        for (int i = 0; i < 4; i++)
            *(uint4*)&vv[i * 8] = *(const uint4*)&base[512 + chq + i * 8];
#pragma unroll
        for (int d = 0; d < 32; d++)
            sVt[d * 264 + s] = vv[d];
    }
    __syncthreads();

    int g = lane >> 2, t = lane & 3;
    int mbase = warp * 32;

    int arow = lane & 15;
    int acol = (lane >> 4) << 3;
    int brow = (lane & 7) + ((lane >> 4) << 3);
    int bcol = (lane & 8) ? 8 : 0;
    uint32_t qBase = (uint32_t)__cvta_generic_to_shared(sQ);
    uint32_t kBase = (uint32_t)__cvta_generic_to_shared(sK);
    uint32_t vBase = (uint32_t)__cvta_generic_to_shared(sVt);

    uint32_t qa[2][2][4];
#pragma unroll
    for (int mt = 0; mt < 2; mt++)
#pragma unroll
        for (int ks = 0; ks < 2; ks++)
            ldsm_x4(qa[mt][ks],
                    qBase + ((mbase + mt * 16 + arow) * 40 + ks * 16 + acol) * 2);

    float o[2][4][4];
#pragma unroll
    for (int i = 0; i < 2; i++)
#pragma unroll
        for (int j = 0; j < 4; j++)
#pragma unroll
            for (int k = 0; k < 4; k++) o[i][j][k] = 0.f;
    float lrow[2][2] = {{0.f, 0.f}, {0.f, 0.f}};

#pragma unroll
    for (int kc = 0; kc < 8; kc++) {
        float sacc[2][4][4];
#pragma unroll
        for (int i = 0; i < 2; i++)
#pragma unroll
            for (int j = 0; j < 4; j++)
#pragma unroll
                for (int k = 0; k < 4; k++) sacc[i][j][k] = 0.f;

#pragma unroll
        for (int ks = 0; ks < 2; ks++) {
            uint32_t kb[4][2];
#pragma unroll
            for (int p = 0; p < 2; p++) {
                uint32_t r4[4];
                ldsm_x4(r4, kBase + ((kc * 32 + p * 16 + brow) * 40 + ks * 16 + bcol) * 2);
                kb[2 * p][0] = r4[0]; kb[2 * p][1] = r4[1];
                kb[2 * p + 1][0] = r4[2]; kb[2 * p + 1][1] = r4[3];
            }
#pragma unroll
            for (int mt = 0; mt < 2; mt++)
#pragma unroll
                for (int nt = 0; nt < 4; nt++)
                    mma_bf16(sacc[mt][nt], qa[mt][ks], kb[nt]);
        }

        // P = exp2(S) via MUFU
#pragma unroll
        for (int mt = 0; mt < 2; mt++)
#pragma unroll
            for (int hi = 0; hi < 2; hi++) {
                float rs = 0.f;
#pragma unroll
                for (int nt = 0; nt < 4; nt++) {
                    float p0 = ex2_fast(sacc[mt][nt][hi * 2]);
                    float p1 = ex2_fast(sacc[mt][nt][hi * 2 + 1]);
                    sacc[mt][nt][hi * 2] = p0;
                    sacc[mt][nt][hi * 2 + 1] = p1;
                    rs += p0 + p1;
                }
                lrow[mt][hi] += rs;
            }

        // O += P V
#pragma unroll
        for (int ksv = 0; ksv < 2; ksv++) {
            uint32_t pa[2][4];
#pragma unroll
            for (int mt = 0; mt < 2; mt++) {
                pa[mt][0] = pack_bf(sacc[mt][2 * ksv][0], sacc[mt][2 * ksv][1]);
                pa[mt][1] = pack_bf(sacc[mt][2 * ksv][2], sacc[mt][2 * ksv][3]);
                pa[mt][2] = pack_bf(sacc[mt][2 * ksv + 1][0], sacc[mt][2 * ksv + 1][1]);
                pa[mt][3] = pack_bf(sacc[mt][2 * ksv + 1][2], sacc[mt][2 * ksv + 1][3]);
            }
            uint32_t vb[4][2];
            int kkv = kc * 32 + ksv * 16;
#pragma unroll
            for (int p = 0; p < 2; p++) {
                uint32_t r4[4];
                ldsm_x4(r4, vBase + ((p * 16 + brow) * 264 + kkv + bcol) * 2);
                vb[2 * p][0] = r4[0]; vb[2 * p][1] = r4[1];
                vb[2 * p + 1][0] = r4[2]; vb[2 * p + 1][1] = r4[3];
            }
#pragma unroll
            for (int mt = 0; mt < 2; mt++)
#pragma unroll
                for (int nt = 0; nt < 4; nt++)
                    mma_bf16(o[mt][nt], pa[mt], vb[nt]);
        }
    }

    // final row-sum reduce, normalize, stage to smem as f16
#pragma unroll
    for (int mt = 0; mt < 2; mt++)
#pragma unroll
        for (int hi = 0; hi < 2; hi++) {
            float l = lrow[mt][hi];
            l += __shfl_xor_sync(0xffffffffu, l, 1);
            l += __shfl_xor_sync(0xffffffffu, l, 2);
            float inv = 1.0f / l;
            int r = mbase + mt * 16 + g + hi * 8;
#pragma unroll
            for (int nt = 0; nt < 4; nt++) {
                *reinterpret_cast<__half2*>(&sO[r * 40 + nt * 8 + t * 2]) =
                    __floats2half2_rn(o[mt][nt][hi * 2] * inv, o[mt][nt][hi * 2 + 1] * inv);
            }
        }
    __syncthreads();

    // cooperative coalesced write to g_h (f16 bits)
#pragma unroll
    for (int i = 0; i < 4; i++) {
        int li = i * 256 + tid;
        int s = li >> 2, seg = li & 3;
        size_t tok;
        if (branch == 0)
            tok = (size_t)(b * 128 + grp * 2) * 128 + s;
        else
            tok = (size_t)(b * 128 + (s & 127)) * 128 + grp * 2 + (s >> 7);
        *(uint4*)&g_h[tok * 256 + chq + seg * 8] = *(const uint4*)&sO[s * 40 + seg * 8];
    }
}

// ---------------------------------------------------------------------------
// launch
// ---------------------------------------------------------------------------
extern "C" void kernel_launch(void* const* d_in, const int* in_sizes, int n_in,
                              void* d_out, int out_size) {
    const float* x     = (const float*)d_in[0];
    const float* Wqkv  = (const float*)d_in[1];
    const float* bqkv  = (const float*)d_in[2];
    const float* Wproj = (const float*)d_in[3];
    const float* bproj = (const float*)d_in[4];
    const float* gamma = (const float*)d_in[5];
    const float* beta  = (const float*)d_in[6];
    float* out = (float*)d_out;

    cudaFuncSetAttribute(gemm0_persist, cudaFuncAttributeMaxDynamicSharedMemorySize, GEMM0_SMEM);
    cudaFuncSetAttribute(gemm1_persist, cudaFuncAttributeMaxDynamicSharedMemorySize, GEMM1_SMEM);
    cudaFuncSetAttribute(attn_kernel, cudaFuncAttributeMaxDynamicSharedMemorySize, ATTN_SMEM);

    prep_weights<<<768, 256>>>(Wqkv, Wproj);
    gemm0_persist<<<TOKENS / 128, 256, GEMM0_SMEM>>>(x, gamma, beta, bqkv);
    attn_kernel<<<4096, 256, ATTN_SMEM>>>();
    gemm1_persist<<<GEMM1_GRID, 256, GEMM1_SMEM>>>(bproj, x, out);
}

// round 16
// speedup vs baseline: 1.0188x; 1.0017x over previous
#include <cuda_runtime.h>
#include <cuda_bf16.h>
#include <cuda_fp16.h>
#include <cstdint>

#define TOKENS 131072            // 8 * 128 * 128
#define DIM 256

// scale * log2(e) folded into Q at GEMM0 epilogue
#define K2SCALE 0.25503837897544077f

// ---------------------------------------------------------------------------
// Scratch (device globals — no cudaMalloc allowed)
// ---------------------------------------------------------------------------
__device__ __nv_bfloat16 g_qkv[(size_t)TOKENS * 3 * DIM];     // 192 MiB (bf16)
__device__ __half g_h[(size_t)TOKENS * DIM];                  //  64 MiB (f16)
__device__ __nv_bfloat16 g_WqkvT[3 * DIM * DIM];              // [768][256] bf16
__device__ __half g_WprojT[DIM * DIM];                        // [256][256] f16

// ---------------------------------------------------------------------------
// PTX helpers
// ---------------------------------------------------------------------------
__device__ __forceinline__ void mma_bf16(float* c, const uint32_t* a, const uint32_t* b) {
    asm("mma.sync.aligned.m16n8k16.row.col.f32.bf16.bf16.f32 "
        "{%0,%1,%2,%3}, {%4,%5,%6,%7}, {%8,%9}, {%0,%1,%2,%3};\n"
        : "+f"(c[0]), "+f"(c[1]), "+f"(c[2]), "+f"(c[3])
        : "r"(a[0]), "r"(a[1]), "r"(a[2]), "r"(a[3]), "r"(b[0]), "r"(b[1]));
}

// f16 x f16 -> f16 accumulate (rate-equal, but halves accumulator registers)
__device__ __forceinline__ void mma_f16acc(uint32_t* c, const uint32_t* a, const uint32_t* b) {
    asm("mma.sync.aligned.m16n8k16.row.col.f16.f16.f16.f16 "
        "{%0,%1}, {%2,%3,%4,%5}, {%6,%7}, {%0,%1};\n"
        : "+r"(c[0]), "+r"(c[1])
        : "r"(a[0]), "r"(a[1]), "r"(a[2]), "r"(a[3]), "r"(b[0]), "r"(b[1]));
}

__device__ __forceinline__ void ldsm_x4(uint32_t* r, uint32_t addr) {
    asm volatile("ldmatrix.sync.aligned.m8n8.x4.shared.b16 {%0,%1,%2,%3}, [%4];"
                 : "=r"(r[0]), "=r"(r[1]), "=r"(r[2]), "=r"(r[3]) : "r"(addr));
}

__device__ __forceinline__ void cp_async16(void* smem_ptr, const void* gmem_ptr) {
    uint32_t s = (uint32_t)__cvta_generic_to_shared(smem_ptr);
    asm volatile("cp.async.cg.shared.global [%0], [%1], 16;\n" :: "r"(s), "l"(gmem_ptr));
}

__device__ __forceinline__ uint32_t pack_bf(float x, float y) {
    __nv_bfloat162 h = __floats2bfloat162_rn(x, y);
    return *reinterpret_cast<uint32_t*>(&h);
}

__device__ __forceinline__ float ex2_fast(float x) {
    float y;
    asm("ex2.approx.f32 %0, %1;" : "=f"(y) : "f"(x));
    return y;
}

// swizzled chunk offsets. A rows = 512B (32 chunks); B rows = 128B (8 chunks).
__device__ __forceinline__ uint32_t a_sw(int row, int c16) {   // bytes
    return (uint32_t)(row * 512 + ((c16 ^ (row & 7)) << 4));
}
__device__ __forceinline__ uint32_t b_sw(int row, int c16) {   // bytes
    return (uint32_t)(row * 128 + ((c16 ^ (row & 7)) << 4));
}

// ---------------------------------------------------------------------------
// Weight prep: Wqkv -> bf16 transpose; Wproj -> f16 transpose (tiny)
// ---------------------------------------------------------------------------
__global__ void prep_weights(const float* __restrict__ Wqkv, const float* __restrict__ Wproj) {
    int n = blockIdx.x;        // 0..767
    int k = threadIdx.x;       // 0..255
    g_WqkvT[n * DIM + k] = __float2bfloat16(Wqkv[(size_t)k * 768 + n]);
    if (n < DIM)
        g_WprojT[n * DIM + k] = __float2half(Wproj[(size_t)k * DIM + n]);
}

// ---------------------------------------------------------------------------
// GEMM0 (bf16, persistent over N, LN fused, 3-stage B pipeline) — R15 state.
// qkv[M,768] = LN(x)[M,256] x Wqkv (+bqkv).
// smem total: 65536 + 49152 = 114688 B  (2 CTAs/SM)
// ---------------------------------------------------------------------------
#define GEMM0_SMEM 114688

__global__ __launch_bounds__(256, 2) void gemm0_persist(const float* __restrict__ x,
                                                        const float* __restrict__ gamma,
                                                        const float* __restrict__ beta,
                                                        const float* __restrict__ bias) {
    extern __shared__ char smraw[];
    __nv_bfloat16* smA = (__nv_bfloat16*)smraw;            // A: [0, 65536) bytes
    char* smB = smraw + 65536;                             // B stage s at s*16384

    int m0 = blockIdx.x * 128;
    int tid = threadIdx.x;
    int lane = tid & 31, warp = tid >> 5;
    int wm = warp >> 2, wn = warp & 3;   // 2 x 4 warp grid
    int g = lane >> 2, t = lane & 3;

    int arow = lane & 15;
    int acol = (lane >> 4) << 3;
    int brow = (lane & 7) + ((lane >> 4) << 3);
    int bcol = (lane & 8) ? 8 : 0;
    uint32_t aBase = (uint32_t)__cvta_generic_to_shared(smraw);
    uint32_t bBase0 = aBase + 65536;

    auto load_B = [&](int f, int st) {     // f -> (it, kb)
        int it = f >> 2, kb = f & 3;
#pragma unroll
        for (int i = 0; i < 4; i++) {
            int li = tid + i * 256;           // 0..1023
            int row = li >> 3, c16 = li & 7;  // 128 rows x 8 chunks
            cp_async16(smB + st * 16384 + b_sw(row, c16),
                       &g_WqkvT[(size_t)(it * 128 + row) * 256 + kb * 64 + c16 * 8]);
        }
        asm volatile("cp.async.commit_group;\n" ::: "memory");
    };

    load_B(0, 0);
    load_B(1, 1);

    // ---- LN prologue: 8 warps x 16 rows, write swizzled bf16 A tile ----
    {
        int c0 = lane * 8;                   // chunk index = lane
        float4 ga = *(const float4*)(gamma + c0);
        float4 gb = *(const float4*)(gamma + c0 + 4);
        float4 ba = *(const float4*)(beta + c0);
        float4 bb = *(const float4*)(beta + c0 + 4);
        float gg[8] = {ga.x, ga.y, ga.z, ga.w, gb.x, gb.y, gb.z, gb.w};
        float be[8] = {ba.x, ba.y, ba.z, ba.w, bb.x, bb.y, bb.z, bb.w};
#pragma unroll 4
        for (int i = 0; i < 16; i++) {
            int row = warp * 16 + i;
            const float* xr = x + (size_t)(m0 + row) * 256 + c0;
            float4 v0 = *(const float4*)xr;
            float4 v1 = *(const float4*)(xr + 4);
            float v[8] = {v0.x, v0.y, v0.z, v0.w, v1.x, v1.y, v1.z, v1.w};
            float s = 0.f, sq = 0.f;
#pragma unroll
            for (int j = 0; j < 8; j++) { s += v[j]; sq += v[j] * v[j]; }
#pragma unroll
            for (int o = 16; o > 0; o >>= 1) {
                s  += __shfl_xor_sync(0xffffffffu, s, o);
                sq += __shfl_xor_sync(0xffffffffu, sq, o);
            }
            float mean = s * (1.0f / DIM);
            float var  = sq * (1.0f / DIM) - mean * mean;
            float rstd = rsqrtf(var + 1e-5f);
            __nv_bfloat16 y[8];
#pragma unroll
            for (int j = 0; j < 8; j++)
                y[j] = __float2bfloat16((v[j] - mean) * rstd * gg[j] + be[j]);
            *(uint4*)((char*)smA + a_sw(row, lane)) = *(uint4*)y;
        }
    }

    float acc[4][4][4];
#pragma unroll
    for (int i = 0; i < 4; i++)
#pragma unroll
        for (int j = 0; j < 4; j++)
#pragma unroll
            for (int k = 0; k < 4; k++) acc[i][j][k] = 0.f;

    for (int f = 0; f < 24; f++) {
        int it = f >> 2, kb = f & 3;
        int st = f % 3;
        if (f + 1 < 24) {
            asm volatile("cp.async.wait_group 1;\n" ::: "memory");
        } else {
            asm volatile("cp.async.wait_group 0;\n" ::: "memory");
        }
        __syncthreads();
        if (f + 2 < 24) load_B(f + 2, (f + 2) % 3);

        uint32_t bB = bBase0 + st * 16384;

#pragma unroll
        for (int ks = 0; ks < 4; ks++) {
            int c16a = (kb * 64 + ks * 16 + acol) >> 3;
            int c16b = (ks * 16 + bcol) >> 3;
            uint32_t af[4][4], bfr[4][2];
#pragma unroll
            for (int mt = 0; mt < 4; mt++) {
                int r = wm * 64 + mt * 16 + arow;
                ldsm_x4(af[mt], aBase + a_sw(r, c16a));
            }
#pragma unroll
            for (int p = 0; p < 2; p++) {
                int r = wn * 32 + p * 16 + brow;
                uint32_t r4[4];
                ldsm_x4(r4, bB + b_sw(r, c16b));
                bfr[2 * p][0] = r4[0]; bfr[2 * p][1] = r4[1];
                bfr[2 * p + 1][0] = r4[2]; bfr[2 * p + 1][1] = r4[3];
            }
#pragma unroll
            for (int mt = 0; mt < 4; mt++)
#pragma unroll
                for (int nt = 0; nt < 4; nt++)
                    mma_bf16(acc[mt][nt], af[mt], bfr[nt]);
        }

        if (kb == 3) {
            int n0 = it * 128;
            float sc = (it < 2) ? K2SCALE : 1.0f;   // Q scaled; K, V plain
#pragma unroll
            for (int mt = 0; mt < 4; mt++) {
                int r = m0 + wm * 64 + mt * 16 + g;
#pragma unroll
                for (int nt = 0; nt < 4; nt++) {
                    int c = n0 + wn * 32 + nt * 8 + t * 2;
                    float b0 = bias[c], b1 = bias[c + 1];
                    *reinterpret_cast<__nv_bfloat162*>(&g_qkv[(size_t)r * 768 + c]) =
                        __floats2bfloat162_rn((acc[mt][nt][0] + b0) * sc,
                                              (acc[mt][nt][1] + b1) * sc);
                    *reinterpret_cast<__nv_bfloat162*>(&g_qkv[(size_t)(r + 8) * 768 + c]) =
                        __floats2bfloat162_rn((acc[mt][nt][2] + b0) * sc,
                                              (acc[mt][nt][3] + b1) * sc);
#pragma unroll
                    for (int k = 0; k < 4; k++) acc[mt][nt][k] = 0.f;
                }
            }
        }
    }
}

// ---------------------------------------------------------------------------
// GEMM1 (f16 x f16 -> f16 accum; R14 measured-best: grid 2048, 64-row
// M-tiles, 2-stage B, 3 CTAs/SM): out[M,256] = h x Wproj + bproj + x.
// smem: A 64x512B swizzled = 32768 + 2 x 16384 B = 65536 B  (3 CTAs/SM)
// ---------------------------------------------------------------------------
#define GEMM1_SMEM 65536

__global__ __launch_bounds__(256, 3) void gemm1_persist(const float* __restrict__ bias,
                                                        const float* __restrict__ resid,
                                                        float* __restrict__ outf) {
    extern __shared__ char smraw[];
    char* smB = smraw + 32768;

    int m0 = blockIdx.x * 64;
    int tid = threadIdx.x;
    int lane = tid & 31, warp = tid >> 5;
    int wm = warp >> 2, wn = warp & 3;   // 2 x 4 warp grid, warp tile 32x32
    int g = lane >> 2, t = lane & 3;

    int arow = lane & 15;
    int acol = (lane >> 4) << 3;
    int brow = (lane & 7) + ((lane >> 4) << 3);
    int bcol = (lane & 8) ? 8 : 0;
    uint32_t aBase = (uint32_t)__cvta_generic_to_shared(smraw);
    uint32_t bBase0 = aBase + 32768;

    auto load_B = [&](int f, int st) {
        int it = f >> 2, kb = f & 3;
#pragma unroll
        for (int i = 0; i < 4; i++) {
            int li = tid + i * 256;
            int row = li >> 3, c16 = li & 7;
            cp_async16(smB + st * 16384 + b_sw(row, c16),
                       &g_WprojT[(size_t)(it * 128 + row) * 256 + kb * 64 + c16 * 8]);
        }
        asm volatile("cp.async.commit_group;\n" ::: "memory");
    };

    load_B(0, 0);

    // ---- load A (once): 64 x 256 f16, swizzled rows ----
#pragma unroll
    for (int i = 0; i < 8; i++) {
        int li = tid + i * 256;            // 0..2047
        int row = li >> 5, c16 = li & 31;
        cp_async16(smraw + a_sw(row, c16),
                   &g_h[(size_t)(m0 + row) * 256 + c16 * 8]);
    }
    asm volatile("cp.async.commit_group;\n" ::: "memory");

    uint32_t acc[2][4][2];   // f16x2 accumulators (16 regs)
#pragma unroll
    for (int i = 0; i < 2; i++)
#pragma unroll
        for (int j = 0; j < 4; j++) { acc[i][j][0] = 0u; acc[i][j][1] = 0u; }

    for (int f = 0; f < 8; f++) {
        int it = f >> 2, kb = f & 3, st = f & 1;
        asm volatile("cp.async.wait_group 0;\n" ::: "memory");
        __syncthreads();
        if (f + 1 < 8) load_B(f + 1, (f + 1) & 1);

        uint32_t bB = bBase0 + st * 16384;

#pragma unroll
        for (int ks = 0; ks < 4; ks++) {
            int c16a = (kb * 64 + ks * 16 + acol) >> 3;
            int c16b = (ks * 16 + bcol) >> 3;
            uint32_t af[2][4], bfr[4][2];
#pragma unroll
            for (int mt = 0; mt < 2; mt++) {
                int r = wm * 32 + mt * 16 + arow;
                ldsm_x4(af[mt], aBase + a_sw(r, c16a));
            }
#pragma unroll
            for (int p = 0; p < 2; p++) {
                int r = wn * 32 + p * 16 + brow;
                uint32_t r4[4];
                ldsm_x4(r4, bB + b_sw(r, c16b));
                bfr[2 * p][0] = r4[0]; bfr[2 * p][1] = r4[1];
                bfr[2 * p + 1][0] = r4[2]; bfr[2 * p + 1][1] = r4[3];
            }
#pragma unroll
            for (int mt = 0; mt < 2; mt++)
#pragma unroll
                for (int nt = 0; nt < 4; nt++)
                    mma_f16acc(acc[mt][nt], af[mt], bfr[nt]);
        }

        if (kb == 3) {
            int n0 = it * 128;
#pragma unroll
            for (int mt = 0; mt < 2; mt++) {
                int r = m0 + wm * 32 + mt * 16 + g;
#pragma unroll
                for (int nt = 0; nt < 4; nt++) {
                    int c = n0 + wn * 32 + nt * 8 + t * 2;
                    float b0 = bias[c], b1 = bias[c + 1];
                    __half2 h0 = *reinterpret_cast<__half2*>(&acc[mt][nt][0]); // row r
                    __half2 h1 = *reinterpret_cast<__half2*>(&acc[mt][nt][1]); // row r+8
                    size_t i0 = (size_t)r * 256 + c;
                    float2 rx0 = *(const float2*)(resid + i0);
                    float2 o0;
                    o0.x = __low2float(h0) + b0 + rx0.x;
                    o0.y = __high2float(h0) + b1 + rx0.y;
                    *(float2*)(outf + i0) = o0;
                    size_t i1 = (size_t)(r + 8) * 256 + c;
                    float2 rx1 = *(const float2*)(resid + i1);
                    float2 o1;
                    o1.x = __low2float(h1) + b0 + rx1.x;
                    o1.y = __high2float(h1) + b1 + rx1.y;
                    *(float2*)(outf + i1) = o1;
                    acc[mt][nt][0] = 0u; acc[mt][nt][1] = 0u;
                }
            }
        }
    }
}

// ---------------------------------------------------------------------------
// Stripe attention (R10 state; output staged/written as f16 for gemm1).
// smem: sQ [256][40] (reused as sO), sK [256][40], sVt [32][264] = 57856 B
// ---------------------------------------------------------------------------
#define ATTN_SMEM 57856

__global__ __launch_bounds__(256, 2) void attn_kernel() {
    extern __shared__ __nv_bfloat16 smA[];
    __nv_bfloat16* sQ  = smA;                    // [256][40]  (reused as sO)
    __nv_bfloat16* sK  = smA + 10240;            // [256][40]
    __nv_bfloat16* sVt = smA + 20480;            // [32][264]  (V transposed)
    __half*        sO  = (__half*)sQ;            // staged output (f16)

    int bid = blockIdx.x;
    int head   = bid & 3;
    int grp    = (bid >> 2) & 63;
    int b      = (bid >> 8) & 7;
    int branch = bid >> 11;                       // 0 = horizontal, 1 = vertical
    int off = branch << 7;                        // 0 or 128
    int chq = off + head * 32;

    int tid = threadIdx.x;
    int lane = tid & 31, warp = tid >> 5;

    {
        int s = tid;  // seq position 0..255
        size_t tok;
        if (branch == 0)
            tok = (size_t)(b * 128 + grp * 2) * 128 + s;
        else
            tok = (size_t)(b * 128 + (s & 127)) * 128 + grp * 2 + (s >> 7);
        const __nv_bfloat16* base = g_qkv + tok * 768;
#pragma unroll
        for (int i = 0; i < 4; i++)
            *(uint4*)&sQ[s * 40 + i * 8] = *(const uint4*)&base[chq + i * 8];
#pragma unroll
        for (int i = 0; i < 4; i++)
            *(uint4*)&sK[s * 40 + i * 8] = *(const uint4*)&base[256 + chq + i * 8];
        __nv_bfloat16 vv[32];
#pragma unroll
        for (int i = 0; i < 4; i++)
            *(uint4*)&vv[i * 8] = *(const uint4*)&base[512 + chq + i * 8];
#pragma unroll
        for (int d = 0; d < 32; d++)
            sVt[d * 264 + s] = vv[d];
    }
    __syncthreads();

    int g = lane >> 2, t = lane & 3;
    int mbase = warp * 32;

    int arow = lane & 15;
    int acol = (lane >> 4) << 3;
    int brow = (lane & 7) + ((lane >> 4) << 3);
    int bcol = (lane & 8) ? 8 : 0;
    uint32_t qBase = (uint32_t)__cvta_generic_to_shared(sQ);
    uint32_t kBase = (uint32_t)__cvta_generic_to_shared(sK);
    uint32_t vBase = (uint32_t)__cvta_generic_to_shared(sVt);

    uint32_t qa[2][2][4];
#pragma unroll
    for (int mt = 0; mt < 2; mt++)
#pragma unroll
        for (int ks = 0; ks < 2; ks++)
            ldsm_x4(qa[mt][ks],
                    qBase + ((mbase + mt * 16 + arow) * 40 + ks * 16 + acol) * 2);

    float o[2][4][4];
#pragma unroll
    for (int i = 0; i < 2; i++)
#pragma unroll
        for (int j = 0; j < 4; j++)
#pragma unroll
            for (int k = 0; k < 4; k++) o[i][j][k] = 0.f;
    float lrow[2][2] = {{0.f, 0.f}, {0.f, 0.f}};

#pragma unroll
    for (int kc = 0; kc < 8; kc++) {
        float sacc[2][4][4];
#pragma unroll
        for (int i = 0; i < 2; i++)
#pragma unroll
            for (int j = 0; j < 4; j++)
#pragma unroll
                for (int k = 0; k < 4; k++) sacc[i][j][k] = 0.f;

#pragma unroll
        for (int ks = 0; ks < 2; ks++) {
            uint32_t kb[4][2];
#pragma unroll
            for (int p = 0; p < 2; p++) {
                uint32_t r4[4];
                ldsm_x4(r4, kBase + ((kc * 32 + p * 16 + brow) * 40 + ks * 16 + bcol) * 2);
                kb[2 * p][0] = r4[0]; kb[2 * p][1] = r4[1];
                kb[2 * p + 1][0] = r4[2]; kb[2 * p + 1][1] = r4[3];
            }
#pragma unroll
            for (int mt = 0; mt < 2; mt++)
#pragma unroll
                for (int nt = 0; nt < 4; nt++)
                    mma_bf16(sacc[mt][nt], qa[mt][ks], kb[nt]);
        }

        // P = exp2(S) via MUFU
#pragma unroll
        for (int mt = 0; mt < 2; mt++)
#pragma unroll
            for (int hi = 0; hi < 2; hi++) {
                float rs = 0.f;
#pragma unroll
                for (int nt = 0; nt < 4; nt++) {
                    float p0 = ex2_fast(sacc[mt][nt][hi * 2]);
                    float p1 = ex2_fast(sacc[mt][nt][hi * 2 + 1]);
                    sacc[mt][nt][hi * 2] = p0;
                    sacc[mt][nt][hi * 2 + 1] = p1;
                    rs += p0 + p1;
                }
                lrow[mt][hi] += rs;
            }

        // O += P V
#pragma unroll
        for (int ksv = 0; ksv < 2; ksv++) {
            uint32_t pa[2][4];
#pragma unroll
            for (int mt = 0; mt < 2; mt++) {
                pa[mt][0] = pack_bf(sacc[mt][2 * ksv][0], sacc[mt][2 * ksv][1]);
                pa[mt][1] = pack_bf(sacc[mt][2 * ksv][2], sacc[mt][2 * ksv][3]);
                pa[mt][2] = pack_bf(sacc[mt][2 * ksv + 1][0], sacc[mt][2 * ksv + 1][1]);
                pa[mt][3] = pack_bf(sacc[mt][2 * ksv + 1][2], sacc[mt][2 * ksv + 1][3]);
            }
            uint32_t vb[4][2];
            int kkv = kc * 32 + ksv * 16;
#pragma unroll
            for (int p = 0; p < 2; p++) {
                uint32_t r4[4];
                ldsm_x4(r4, vBase + ((p * 16 + brow) * 264 + kkv + bcol) * 2);
                vb[2 * p][0] = r4[0]; vb[2 * p][1] = r4[1];
                vb[2 * p + 1][0] = r4[2]; vb[2 * p + 1][1] = r4[3];
            }
#pragma unroll
            for (int mt = 0; mt < 2; mt++)
#pragma unroll
                for (int nt = 0; nt < 4; nt++)
                    mma_bf16(o[mt][nt], pa[mt], vb[nt]);
        }
    }

    // final row-sum reduce, normalize, stage to smem as f16
#pragma unroll
    for (int mt = 0; mt < 2; mt++)
#pragma unroll
        for (int hi = 0; hi < 2; hi++) {
            float l = lrow[mt][hi];
            l += __shfl_xor_sync(0xffffffffu, l, 1);
            l += __shfl_xor_sync(0xffffffffu, l, 2);
            float inv = 1.0f / l;
            int r = mbase + mt * 16 + g + hi * 8;
#pragma unroll
            for (int nt = 0; nt < 4; nt++) {
                *reinterpret_cast<__half2*>(&sO[r * 40 + nt * 8 + t * 2]) =
                    __floats2half2_rn(o[mt][nt][hi * 2] * inv, o[mt][nt][hi * 2 + 1] * inv);
            }
        }
    __syncthreads();

    // cooperative coalesced write to g_h (f16 bits)
#pragma unroll
    for (int i = 0; i < 4; i++) {
        int li = i * 256 + tid;
        int s = li >> 2, seg = li & 3;
        size_t tok;
        if (branch == 0)
            tok = (size_t)(b * 128 + grp * 2) * 128 + s;
        else
            tok = (size_t)(b * 128 + (s & 127)) * 128 + grp * 2 + (s >> 7);
        *(uint4*)&g_h[tok * 256 + chq + seg * 8] = *(const uint4*)&sO[s * 40 + seg * 8];
    }
}

// ---------------------------------------------------------------------------
// launch
// ---------------------------------------------------------------------------
extern "C" void kernel_launch(void* const* d_in, const int* in_sizes, int n_in,
                              void* d_out, int out_size) {
    const float* x     = (const float*)d_in[0];
    const float* Wqkv  = (const float*)d_in[1];
    const float* bqkv  = (const float*)d_in[2];
    const float* Wproj = (const float*)d_in[3];
    const float* bproj = (const float*)d_in[4];
    const float* gamma = (const float*)d_in[5];
    const float* beta  = (const float*)d_in[6];
    float* out = (float*)d_out;

    cudaFuncSetAttribute(gemm0_persist, cudaFuncAttributeMaxDynamicSharedMemorySize, GEMM0_SMEM);
    cudaFuncSetAttribute(gemm1_persist, cudaFuncAttributeMaxDynamicSharedMemorySize, GEMM1_SMEM);
    cudaFuncSetAttribute(attn_kernel, cudaFuncAttributeMaxDynamicSharedMemorySize, ATTN_SMEM);

    prep_weights<<<768, 256>>>(Wqkv, Wproj);
    gemm0_persist<<<TOKENS / 128, 256, GEMM0_SMEM>>>(x, gamma, beta, bqkv);
    attn_kernel<<<4096, 256, ATTN_SMEM>>>();
    gemm1_persist<<<TOKENS / 64, 256, GEMM1_SMEM>>>(bproj, x, out);
}